// round 12
// baseline (speedup 1.0000x reference)
#include <cuda_runtime.h>
#include <cuda_bf16.h>

typedef unsigned int u32;
typedef unsigned long long u64;

// Problem constants
#define BB 8
#define CC 32
#define PP 128
#define DD 256
#define HH 8
#define RR 32
#define NT (BB*CC)
#define NC (BB*PP)
#define ROWS 32768
#define OUT_HALF (BB*CC*PP*DD)

// ---------------- scratch ----------------
__device__ __align__(256) float d_qur_t[NT*HH*PP*RR];
__device__ __align__(256) float d_quo_t[NT*HH*PP*RR];
__device__ __align__(256) float d_qvr_t[NT*HH*PP*RR];
__device__ __align__(256) float d_qur_c[NC*HH*CC*RR];
__device__ __align__(256) float d_quo_c[NC*HH*CC*RR];
__device__ __align__(256) float d_qvr_c[NC*HH*CC*RR];
__device__ __align__(256) float d_F_t[NT*HH*PP*PP];
__device__ __align__(256) float d_F_c[NC*HH*CC*CC];
__device__ __align__(256) float d_cos[PP*16];
__device__ __align__(256) float d_sin[PP*16];

__device__ __align__(256) __nv_bfloat16 d_qz0[ROWS*256];
__device__ __align__(256) __nv_bfloat16 d_qz1[ROWS*256];
__device__ __align__(256) __nv_bfloat16 d_qz2[ROWS*256];
__device__ __align__(256) __nv_bfloat16 d_wp_t[3][512*256];
__device__ __align__(256) __nv_bfloat16 d_wp_c[3][512*256];
__device__ __align__(256) __nv_bfloat16 d_wf_t[2][256*512];
__device__ __align__(256) __nv_bfloat16 d_wf_c[2][256*512];
__device__ __align__(256) __nv_bfloat16 d_ga0_t[ROWS*512];
__device__ __align__(256) __nv_bfloat16 d_ga1_t[ROWS*512];
__device__ __align__(256) __nv_bfloat16 d_ga0_c[ROWS*512];
__device__ __align__(256) __nv_bfloat16 d_ga1_c[ROWS*512];

// ---------------- HMMA + cp.async helpers (baseline PTX) -------------------
__device__ __forceinline__ void ldm_x4(u32* r, u32 addr) {
    asm volatile("ldmatrix.sync.aligned.m8n8.x4.shared.b16 {%0, %1, %2, %3}, [%4];" : "=r"(r[0]), "=r"(r[1]), "=r"(r[2]), "=r"(r[3]) : "r"(addr));
}
__device__ __forceinline__ void mma_bf16(float* d, const u32* a, const u32* b) {
    asm volatile("mma.sync.aligned.m16n8k16.row.col.f32.bf16.bf16.f32 {%0, %1, %2, %3}, {%4, %5, %6, %7}, {%8, %9}, {%0, %1, %2, %3};" : "+f"(d[0]), "+f"(d[1]), "+f"(d[2]), "+f"(d[3]) : "r"(a[0]), "r"(a[1]), "r"(a[2]), "r"(a[3]), "r"(b[0]), "r"(b[1]));
}
__device__ __forceinline__ void cpa(u32 s, const __nv_bfloat16* g) {
    asm volatile("cp.async.ca.shared.global [%0], [%1], 16;" :: "r"(s), "l"((u64)__cvta_generic_to_global((void*)g)) : "memory");
}
__device__ __forceinline__ void cpa_commit() { asm volatile("cp.async.commit_group;" ::: "memory"); }
__device__ __forceinline__ void cpa_wait0() { asm volatile("cp.async.wait_group 0;" ::: "memory"); }
__device__ __forceinline__ void cpa_wait1() { asm volatile("cp.async.wait_group 1;" ::: "memory"); }

#define TILE_BYTES 10240        // 128 rows * 80 bytes
#define PROJ_SMEM (2*6*TILE_BYTES)
#define FIN_SMEM  (2*4*TILE_BYTES)

// k_gt_mma smem layout (stride 272 B = 136 bf16)
#define QH0  0
#define QH1  34816
#define QHT0 69632
#define QHT1 104448
#define VT0  139264
#define VT1  147968
#define UT0  156672
#define UT1  165376
#define GT_SMEM 174080

__device__ __forceinline__ void st_split(__nv_bfloat16* A0, __nv_bfloat16* A1,
                                         long long i, float x) {
    __nv_bfloat16 b0 = __float2bfloat16(x);
    A0[i] = b0;
    A1[i] = __float2bfloat16(x - __bfloat162float(b0));
}

// ---------------- rope table ----------------
__global__ void k_setup() {
    int idx = blockIdx.x * blockDim.x + threadIdx.x;
    if (idx < PP*16) {
        int s = idx >> 4, i = idx & 15;
        double invf = pow(10000.0, -((double)(2*i)) / 32.0);
        double a = (double)s * invf;
        d_cos[idx] = (float)cos(a);
        d_sin[idx] = (float)sin(a);
    }
}

// ---------------- split qz into 3 bf16 components --------------------------
__global__ __launch_bounds__(256) void k_split_qz(const float* __restrict__ qz) {
    int i = (blockIdx.x * 256 + threadIdx.x) * 4;
    float4 x = *reinterpret_cast<const float4*>(qz + i);
    float xs[4];
    xs[0] = x.x; xs[1] = x.y; xs[2] = x.z; xs[3] = x.w;
    __align__(8) __nv_bfloat16 b0[4], b1[4], b2[4];
#pragma unroll
    for (int j = 0; j < 4; j++) {
        b0[j] = __float2bfloat16(xs[j]);
        float r = xs[j] - __bfloat162float(b0[j]);
        b1[j] = __float2bfloat16(r);
        b2[j] = __float2bfloat16(r - __bfloat162float(b1[j]));
    }
    *reinterpret_cast<uint2*>(&d_qz0[i]) = *reinterpret_cast<uint2*>(b0);
    *reinterpret_cast<uint2*>(&d_qz1[i]) = *reinterpret_cast<uint2*>(b1);
    *reinterpret_cast<uint2*>(&d_qz2[i]) = *reinterpret_cast<uint2*>(b2);
}

__global__ __launch_bounds__(256) void k_split_w(const float* __restrict__ U,
                                                 const float* __restrict__ V, int branch) {
    int idx = blockIdx.x * 256 + threadIdx.x;
    int n = idx >> 8, k = idx & 255;
    float x = (n < 256) ? U[n*256 + k] : V[(n-256)*256 + k];
    __nv_bfloat16* w0 = branch ? d_wp_c[0] : d_wp_t[0];
    __nv_bfloat16* w1 = branch ? d_wp_c[1] : d_wp_t[1];
    __nv_bfloat16* w2 = branch ? d_wp_c[2] : d_wp_t[2];
    __nv_bfloat16 b0 = __float2bfloat16(x);
    float r = x - __bfloat162float(b0);
    __nv_bfloat16 b1 = __float2bfloat16(r);
    w0[idx] = b0; w1[idx] = b1;
    w2[idx] = __float2bfloat16(r - __bfloat162float(b1));
}

__global__ __launch_bounds__(256) void k_split_wf(const float* __restrict__ U,
                                                  const float* __restrict__ V, int branch) {
    int idx = blockIdx.x * 256 + threadIdx.x;
    int n = idx >> 9, k = idx & 511;
    float x = (k < 256) ? U[k*256 + n] : V[(k-256)*256 + n];
    __nv_bfloat16* w0 = branch ? d_wf_c[0] : d_wf_t[0];
    __nv_bfloat16* w1 = branch ? d_wf_c[1] : d_wf_t[1];
    __nv_bfloat16 b0 = __float2bfloat16(x);
    w0[idx] = b0;
    w1[idx] = __float2bfloat16(x - __bfloat162float(b0));
}

// ---------------- proj GEMM (HMMA, cp.async pipeline, fused RoPE) ----------
__global__ __launch_bounds__(256, 1) void k_proj_mma(int branch) {
    extern __shared__ char smem[];
    const int tid = threadIdx.x;
    const u32 sbase = (u32)__cvta_generic_to_shared(smem);
    const int n0 = blockIdx.x * 128;
    const int m0 = blockIdx.y * 128;
    const int lane = tid & 31, warp = tid >> 5;
    const int wm = warp >> 1, wn = warp & 1;
    const __nv_bfloat16* W0 = branch ? d_wp_c[0] : d_wp_t[0];
    const __nv_bfloat16* W1 = branch ? d_wp_c[1] : d_wp_t[1];
    const __nv_bfloat16* W2 = branch ? d_wp_c[2] : d_wp_t[2];

    float acc[2][8][4];
#pragma unroll
    for (int mt = 0; mt < 2; mt++)
#pragma unroll
        for (int nt = 0; nt < 8; nt++)
#pragma unroll
            for (int e = 0; e < 4; e++) acc[mt][nt][e] = 0.f;

#pragma unroll 1
    for (int kc = -1; kc < 8; kc++) {
        int ld = kc + 1;
        if (ld < 8) {
            u32 stb = sbase + (u32)(ld & 1) * (6*TILE_BYTES);
#pragma unroll
            for (int t = 0; t < 12; t++) {
                int li = tid + t * 256;
                int seg = li & 3, row = (li >> 2) & 127, tile = li >> 9;
                const __nv_bfloat16* src;
                if (tile < 3) {
                    int grow = m0 + row;
                    if (branch) {
                        int b = grow >> 12, rem = grow & 4095;
                        grow = ((b << 5) + (rem & 31)) * 128 + (rem >> 5);
                    }
                    const __nv_bfloat16* A = (tile == 0) ? d_qz0 : (tile == 1) ? d_qz1 : d_qz2;
                    src = A + (long long)grow * 256 + ld * 32 + seg * 8;
                } else {
                    const __nv_bfloat16* W = (tile == 3) ? W0 : (tile == 4) ? W1 : W2;
                    src = W + (long long)(n0 + row) * 256 + ld * 32 + seg * 8;
                }
                cpa(stb + (u32)(tile * TILE_BYTES + row * 80 + seg * 16), src);
            }
            cpa_commit();
        }
        if (kc < 0) continue;
        if (kc < 7) cpa_wait1(); else cpa_wait0();
        __syncthreads();
        u32 stb = sbase + (u32)(kc & 1) * (6*TILE_BYTES);
#pragma unroll
        for (int ks = 0; ks < 2; ks++) {
            u32 afr[3][2][4];
#pragma unroll
            for (int sp = 0; sp < 3; sp++)
#pragma unroll
                for (int mt = 0; mt < 2; mt++) {
                    u32 addr = stb + sp * TILE_BYTES
                             + (wm * 32 + mt * 16 + (lane & 15)) * 80
                             + ks * 32 + (lane >> 4) * 16;
                    ldm_x4(afr[sp][mt], addr);
                }
#pragma unroll
            for (int sb = 0; sb < 3; sb++) {
                u32 bfr[8][2];
#pragma unroll
                for (int g = 0; g < 4; g++) {
                    u32 tr[4];
                    u32 addr = stb + (3 + sb) * TILE_BYTES
                             + (wn * 64 + g * 16 + (lane & 15)) * 80
                             + ks * 32 + (lane >> 4) * 16;
                    ldm_x4(tr, addr);
                    bfr[2*g][0] = tr[0];   bfr[2*g][1] = tr[2];
                    bfr[2*g+1][0] = tr[1]; bfr[2*g+1][1] = tr[3];
                }
                int na = 3 - sb;
#pragma unroll
                for (int sa = 0; sa < 3; sa++) {
                    if (sa < na) {
#pragma unroll
                        for (int mt = 0; mt < 2; mt++)
#pragma unroll
                            for (int nt = 0; nt < 8; nt++)
                                mma_bf16(acc[mt][nt], afr[sa][mt], bfr[nt]);
                    }
                }
            }
        }
        __syncthreads();
    }

    // fused RoPE epilogue
    float* OUR = branch ? d_qur_c : d_qur_t;
    float* OUO = branch ? d_quo_c : d_quo_t;
    float* OVR = branch ? d_qvr_c : d_qvr_t;
    const int Sbits = branch ? 5 : 7;
    const int Smask = (1 << Sbits) - 1;
    const int isQV = (n0 >= 256);
#pragma unroll
    for (int mt = 0; mt < 2; mt++) {
        int rA = m0 + wm * 32 + mt * 16 + (lane >> 2);
        int rB = rA + 8;
        int nA = rA >> Sbits, sA = rA & Smask;
        int nB = rB >> Sbits, sB = rB & Smask;
#pragma unroll
        for (int nt = 0; nt < 8; nt++) {
            int colh = (n0 & 255) + wn * 64 + nt * 8;
            int rr = (colh & 31) + (lane & 3) * 2;
            int h = (colh >> 5) & 7;
            float sgn = (rr < 16) ? -1.f : 1.f;
            int ci = rr & 15;
            float cA0 = d_cos[sA*16 + ci],     snA0 = d_sin[sA*16 + ci];
            float cA1 = d_cos[sA*16 + ci + 1], snA1 = d_sin[sA*16 + ci + 1];
            float cB0 = d_cos[sB*16 + ci],     snB0 = d_sin[sB*16 + ci];
            float cB1 = d_cos[sB*16 + ci + 1], snB1 = d_sin[sB*16 + ci + 1];
            float q0 = acc[mt][nt][0], q1 = acc[mt][nt][1];
            float q2 = acc[mt][nt][2], q3 = acc[mt][nt][3];
            float p0 = acc[mt][nt ^ 2][0], p1 = acc[mt][nt ^ 2][1];
            float p2 = acc[mt][nt ^ 2][2], p3 = acc[mt][nt ^ 2][3];
            long long baseA = (((long long)(nA * 8 + h) << Sbits) + sA) * 32 + rr;
            long long baseB = (((long long)(nB * 8 + h) << Sbits) + sB) * 32 + rr;
            if (!isQV) {
                float2 w;
                w.x = q0*cA0 + sgn*p0*snA0; w.y = q1*cA1 + sgn*p1*snA1;
                *reinterpret_cast<float2*>(&OUR[baseA]) = w;
                w.x = q0*cA0 - sgn*p0*snA0; w.y = q1*cA1 - sgn*p1*snA1;
                *reinterpret_cast<float2*>(&OUO[baseA]) = w;
                w.x = q2*cB0 + sgn*p2*snB0; w.y = q3*cB1 + sgn*p3*snB1;
                *reinterpret_cast<float2*>(&OUR[baseB]) = w;
                w.x = q2*cB0 - sgn*p2*snB0; w.y = q3*cB1 - sgn*p3*snB1;
                *reinterpret_cast<float2*>(&OUO[baseB]) = w;
            } else {
                float2 w;
                w.x = q0*cA0 + sgn*p0*snA0; w.y = q1*cA1 + sgn*p1*snA1;
                *reinterpret_cast<float2*>(&OVR[baseA]) = w;
                w.x = q2*cB0 + sgn*p2*snB0; w.y = q3*cB1 + sgn*p3*snB1;
                *reinterpret_cast<float2*>(&OVR[baseB]) = w;
            }
        }
    }
}

// ---------------- final GEMM (HMMA, cp.async pipeline) ---------------------
__global__ __launch_bounds__(256, 1) void k_final_mma(float* __restrict__ out, int branch) {
    extern __shared__ char smem[];
    const int tid = threadIdx.x;
    const u32 sbase = (u32)__cvta_generic_to_shared(smem);
    const int n0 = blockIdx.x * 128;
    const int m0 = blockIdx.y * 128;
    const int lane = tid & 31, warp = tid >> 5;
    const int wm = warp >> 1, wn = warp & 1;
    const __nv_bfloat16* G0 = branch ? d_ga0_c : d_ga0_t;
    const __nv_bfloat16* G1 = branch ? d_ga1_c : d_ga1_t;
    const __nv_bfloat16* F0 = branch ? d_wf_c[0] : d_wf_t[0];
    const __nv_bfloat16* F1 = branch ? d_wf_c[1] : d_wf_t[1];

    float acc[2][8][4];
#pragma unroll
    for (int mt = 0; mt < 2; mt++)
#pragma unroll
        for (int nt = 0; nt < 8; nt++)
#pragma unroll
            for (int e = 0; e < 4; e++) acc[mt][nt][e] = 0.f;

#pragma unroll 1
    for (int kc = -1; kc < 16; kc++) {
        int ld = kc + 1;
        if (ld < 16) {
            u32 stb = sbase + (u32)(ld & 1) * (4*TILE_BYTES);
#pragma unroll
            for (int t = 0; t < 8; t++) {
                int li = tid + t * 256;
                int seg = li & 3, row = (li >> 2) & 127, tile = li >> 9;
                const __nv_bfloat16* src;
                if (tile == 0)      src = G0 + (long long)(m0 + row) * 512 + ld * 32 + seg * 8;
                else if (tile == 1) src = G1 + (long long)(m0 + row) * 512 + ld * 32 + seg * 8;
                else if (tile == 2) src = F0 + (long long)(n0 + row) * 512 + ld * 32 + seg * 8;
                else                src = F1 + (long long)(n0 + row) * 512 + ld * 32 + seg * 8;
                cpa(stb + (u32)(tile * TILE_BYTES + row * 80 + seg * 16), src);
            }
            cpa_commit();
        }
        if (kc < 0) continue;
        if (kc < 15) cpa_wait1(); else cpa_wait0();
        __syncthreads();
        u32 stb = sbase + (u32)(kc & 1) * (4*TILE_BYTES);
#pragma unroll
        for (int ks = 0; ks < 2; ks++) {
            u32 afr[2][2][4];
#pragma unroll
            for (int sp = 0; sp < 2; sp++)
#pragma unroll
                for (int mt = 0; mt < 2; mt++) {
                    u32 addr = stb + sp * TILE_BYTES
                             + (wm * 32 + mt * 16 + (lane & 15)) * 80
                             + ks * 32 + (lane >> 4) * 16;
                    ldm_x4(afr[sp][mt], addr);
                }
#pragma unroll
            for (int sb = 0; sb < 2; sb++) {
                u32 bfr[8][2];
#pragma unroll
                for (int g = 0; g < 4; g++) {
                    u32 tr[4];
                    u32 addr = stb + (2 + sb) * TILE_BYTES
                             + (wn * 64 + g * 16 + (lane & 15)) * 80
                             + ks * 32 + (lane >> 4) * 16;
                    ldm_x4(tr, addr);
                    bfr[2*g][0] = tr[0];   bfr[2*g][1] = tr[2];
                    bfr[2*g+1][0] = tr[1]; bfr[2*g+1][1] = tr[3];
                }
                int na = 2 - sb;
#pragma unroll
                for (int sa = 0; sa < 2; sa++) {
                    if (sa < na) {
#pragma unroll
                        for (int mt = 0; mt < 2; mt++)
#pragma unroll
                            for (int nt = 0; nt < 8; nt++)
                                mma_bf16(acc[mt][nt], afr[sa][mt], bfr[nt]);
                    }
                }
            }
        }
        __syncthreads();
    }
#pragma unroll
    for (int mt = 0; mt < 2; mt++)
#pragma unroll
        for (int nt = 0; nt < 8; nt++) {
            int r = m0 + wm * 32 + mt * 16 + (lane >> 2);
            int c = n0 + wn * 64 + nt * 8 + (lane & 3) * 2;
            long long r0o, r1o;
            if (!branch) {
                r0o = (long long)r; r1o = (long long)(r + 8);
            } else {
                int nn = r >> 5, cc2 = r & 31;
                int b = nn >> 7, p = nn & 127;
                r0o = (long long)((b * 32 + cc2) * 128 + p);
                int r8 = r + 8;
                nn = r8 >> 5; cc2 = r8 & 31; b = nn >> 7; p = nn & 127;
                r1o = (long long)((b * 32 + cc2) * 128 + p);
            }
            float2 lo; lo.x = acc[mt][nt][0]; lo.y = acc[mt][nt][1];
            float2 hi; hi.x = acc[mt][nt][2]; hi.y = acc[mt][nt][3];
            *reinterpret_cast<float2*>(&out[r0o * 256 + c]) = lo;
            *reinterpret_cast<float2*>(&out[r1o * 256 + c]) = hi;
        }
}

// ---------------- F_t -------------------------------------------------------
__global__ __launch_bounds__(256) void k_ft(const float* __restrict__ mask) {
    __shared__ float SuT[32][132];
    __shared__ float SvT[32][132];
    int nh = blockIdx.x;
    int n = nh >> 3;
    const float* ubase = d_qur_t + nh*128*32;
    const float* vbase = d_qvr_t + nh*128*32;
    int tid = threadIdx.x;
#pragma unroll
    for (int l = 0; l < 4; l++) {
        int lin = tid + l*256;
        int s = lin >> 3, rq = (lin & 7) << 2;
        float4 u = *reinterpret_cast<const float4*>(ubase + s*32 + rq);
        SuT[rq][s] = u.x; SuT[rq+1][s] = u.y; SuT[rq+2][s] = u.z; SuT[rq+3][s] = u.w;
        float4 v = *reinterpret_cast<const float4*>(vbase + s*32 + rq);
        SvT[rq][s] = v.x; SvT[rq+1][s] = v.y; SvT[rq+2][s] = v.z; SvT[rq+3][s] = v.w;
    }
    __syncthreads();
    int tx = tid & 15, ty = tid >> 4;
    float acc[8][8];
#pragma unroll
    for (int i = 0; i < 8; i++)
#pragma unroll
        for (int j = 0; j < 8; j++) acc[i][j] = 0.f;
#pragma unroll
    for (int k = 0; k < 32; k++) {
        float a[8], b[8];
        *(float4*)&a[0] = *(const float4*)&SuT[k][ty*8];
        *(float4*)&a[4] = *(const float4*)&SuT[k][ty*8+4];
        *(float4*)&b[0] = *(const float4*)&SvT[k][tx*8];
        *(float4*)&b[4] = *(const float4*)&SvT[k][tx*8+4];
#pragma unroll
        for (int i = 0; i < 8; i++)
#pragma unroll
            for (int j = 0; j < 8; j++) acc[i][j] += a[i]*b[j];
    }
    float* fout = d_F_t + (long long)nh*16384;
    const float* mrow = mask + (long long)n*16384;
#pragma unroll
    for (int i = 0; i < 8; i++) {
        int s = ty*8 + i;
#pragma unroll
        for (int j4 = 0; j4 < 2; j4++) {
            int t = tx*8 + j4*4;
            float4 m4 = *reinterpret_cast<const float4*>(mrow + s*128 + t);
            float4 o;
            o.x = acc[i][j4*4]   + m4.x;
            o.y = acc[i][j4*4+1] + m4.y;
            o.z = acc[i][j4*4+2] + m4.z;
            o.w = acc[i][j4*4+3] + m4.w;
            *reinterpret_cast<float4*>(fout + s*128 + t) = o;
        }
    }
}

// ---------------- F_c -------------------------------------------------------
__global__ __launch_bounds__(256) void k_fc(const float* __restrict__ mask) {
    __shared__ float SuT[32][36];
    __shared__ float SvT[32][36];
    int nh = blockIdx.x;
    int n = nh >> 3;
    const float* ubase = d_qur_c + nh*1024;
    const float* vbase = d_qvr_c + nh*1024;
    int tid = threadIdx.x;
    {
        int s = tid >> 3, rq = (tid & 7) << 2;
        float4 u = *reinterpret_cast<const float4*>(ubase + s*32 + rq);
        SuT[rq][s] = u.x; SuT[rq+1][s] = u.y; SuT[rq+2][s] = u.z; SuT[rq+3][s] = u.w;
        float4 v = *reinterpret_cast<const float4*>(vbase + s*32 + rq);
        SvT[rq][s] = v.x; SvT[rq+1][s] = v.y; SvT[rq+2][s] = v.z; SvT[rq+3][s] = v.w;
    }
    __syncthreads();
    int tx = tid & 7, ty = tid >> 3;
    float acc[4];
    acc[0] = 0.f; acc[1] = 0.f; acc[2] = 0.f; acc[3] = 0.f;
#pragma unroll
    for (int k = 0; k < 32; k++) {
        float a = SuT[k][ty];
        float4 b = *(const float4*)&SvT[k][tx*4];
        acc[0] += a*b.x; acc[1] += a*b.y; acc[2] += a*b.z; acc[3] += a*b.w;
    }
    int t0 = tx*4;
    float4 m4 = *reinterpret_cast<const float4*>(mask + (long long)n*1024 + ty*32 + t0);
    float4 o;
    o.x = acc[0] + m4.x; o.y = acc[1] + m4.y; o.z = acc[2] + m4.z; o.w = acc[3] + m4.w;
    *reinterpret_cast<float4*>(d_F_c + (long long)nh*1024 + ty*32 + t0) = o;
}

// ---------------- joint softmax --------------------------------------------
__global__ __launch_bounds__(256) void k_softmax() {
    int warp = threadIdx.x >> 5, lane = threadIdx.x & 31;
    int rowid = blockIdx.x * 8 + warp;
    int p  = rowid & 127;
    int r1 = rowid >> 7;
    int c  = r1 & 31;
    int r2 = r1 >> 5;
    int h  = r2 & 7;
    int b  = r2 >> 3;
    float* ft = d_F_t + ((long long)(((b*32 + c)*8 + h)*128 + p))*128;
    float* fc = d_F_c + ((long long)(((b*128 + p)*8 + h)*32 + c))*32;
    float v[5];
    v[0] = ft[lane]; v[1] = ft[lane+32]; v[2] = ft[lane+64]; v[3] = ft[lane+96];
    v[4] = fc[lane];
    float m = v[0];
#pragma unroll
    for (int i = 1; i < 5; i++) m = fmaxf(m, v[i]);
#pragma unroll
    for (int off = 16; off >= 1; off >>= 1)
        m = fmaxf(m, __shfl_xor_sync(0xffffffffu, m, off));
    float sum = 0.f;
#pragma unroll
    for (int i = 0; i < 5; i++) { v[i] = expf(256.f*(v[i] - m)); sum += v[i]; }
#pragma unroll
    for (int off = 16; off >= 1; off >>= 1)
        sum += __shfl_xor_sync(0xffffffffu, sum, off);
    float inv = 1.f / sum;
    ft[lane]     = v[0]*inv;
    ft[lane+32]  = v[1]*inv;
    ft[lane+64]  = v[2]*inv;
    ft[lane+96]  = v[3]*inv;
    fc[lane]     = v[4]*inv;
}

// ---------------- G time (HMMA, in-kernel 2-way splits) --------------------
// G1: g1[s][r] = sum_t qh[s][t] * qvr[t][r]     (A=qh, B=vT)
// G2: C2[r][s] = sum_t quo[t][r] * qh[t][s]     (A=uT, B=qhT)
__global__ __launch_bounds__(256, 1) void k_gt_mma() {
    extern __shared__ char smem[];
    const int tid = threadIdx.x;
    const u32 sbase = (u32)__cvta_generic_to_shared(smem);
    int nh = blockIdx.x;
    int n = nh >> 3, h = nh & 7;
    const float* qh = d_F_t + (long long)nh*16384;
    const float* vb = d_qvr_t + nh*4096;
    const float* ub = d_quo_t + nh*4096;
    const int lane = tid & 31, warp = tid >> 5;

    // load + split qh -> QH (natural) and QHT (transposed), bf16 x2 each
#pragma unroll
    for (int t = 0; t < 16; t++) {
        int li = tid + t * 256;
        int row = li >> 5, c4 = li & 31;
        float4 x = *reinterpret_cast<const float4*>(qh + row*128 + c4*4);
        float xs[4];
        xs[0] = x.x; xs[1] = x.y; xs[2] = x.z; xs[3] = x.w;
        __align__(8) __nv_bfloat16 b0[4], b1[4];
#pragma unroll
        for (int j = 0; j < 4; j++) {
            b0[j] = __float2bfloat16(xs[j]);
            b1[j] = __float2bfloat16(xs[j] - __bfloat162float(b0[j]));
        }
        int off = row*272 + c4*8;
        *reinterpret_cast<uint2*>(smem + QH0 + off) = *reinterpret_cast<uint2*>(b0);
        *reinterpret_cast<uint2*>(smem + QH1 + off) = *reinterpret_cast<uint2*>(b1);
#pragma unroll
        for (int j = 0; j < 4; j++) {
            int c = c4*4 + j;
            *reinterpret_cast<__nv_bfloat16*>(smem + QHT0 + c*272 + row*2) = b0[j];
            *reinterpret_cast<__nv_bfloat16*>(smem + QHT1 + c*272 + row*2) = b1[j];
        }
    }
    // load + split + transpose v,u -> [32][136] bf16 x2 each
#pragma unroll
    for (int t = 0; t < 2; t++) {
        int li = tid + t * 256;
        int tile = li >> 8;
        int li2 = li & 255;
        int trow = li2 >> 1;
        int half = li2 & 1;
        const float* src = (tile ? ub : vb) + trow*32 + half*16;
        int base0 = tile ? UT0 : VT0;
        int base1 = tile ? UT1 : VT1;
#pragma unroll
        for (int e = 0; e < 16; e++) {
            float x = src[e];
            int r = half*16 + e;
            __nv_bfloat16 b0 = __float2bfloat16(x);
            __nv_bfloat16 b1 = __float2bfloat16(x - __bfloat162float(b0));
            *reinterpret_cast<__nv_bfloat16*>(smem + base0 + r*272 + trow*2) = b0;
            *reinterpret_cast<__nv_bfloat16*>(smem + base1 + r*272 + trow*2) = b1;
        }
    }
    __syncthreads();

    float acc[2][4][4];
#pragma unroll
    for (int mt = 0; mt < 2; mt++)
#pragma unroll
        for (int nt = 0; nt < 4; nt++)
#pragma unroll
            for (int e = 0; e < 4; e++) acc[mt][nt][e] = 0.f;

    if (warp < 4) {
        // G1: A = qh [s][t], B = vT [r][t]
        u32 wbase = (u32)warp * 32;
#pragma unroll
        for (int k0 = 0; k0 < 8; k0++) {
            u32 a[2][2][4];
#pragma unroll
            for (int sp = 0; sp < 2; sp++)
#pragma unroll
                for (int mt = 0; mt < 2; mt++)
                    ldm_x4(a[sp][mt], sbase + (sp ? QH1 : QH0)
                           + (wbase + mt*16 + (lane & 15))*272 + k0*32 + (lane >> 4)*16);
            u32 b[2][4][2];
#pragma unroll
            for (int sp = 0; sp < 2; sp++)
#pragma unroll
                for (int g = 0; g < 2; g++) {
                    u32 tr[4];
                    ldm_x4(tr, sbase + (sp ? VT1 : VT0)
                           + (g*16 + (lane & 15))*272 + k0*32 + (lane >> 4)*16);
                    b[sp][2*g][0] = tr[0];   b[sp][2*g][1] = tr[2];
                    b[sp][2*g+1][0] = tr[1]; b[sp][2*g+1][1] = tr[3];
                }
#pragma unroll
            for (int mt = 0; mt < 2; mt++)
#pragma unroll
                for (int nt = 0; nt < 4; nt++) {
                    mma_bf16(acc[mt][nt], a[0][mt], b[0][nt]);
                    mma_bf16(acc[mt][nt], a[0][mt], b[1][nt]);
                    mma_bf16(acc[mt][nt], a[1][mt], b[0][nt]);
                }
        }
#pragma unroll
        for (int mt = 0; mt < 2; mt++) {
            int s0 = (int)wbase + mt*16 + (lane >> 2);
#pragma unroll
            for (int nt = 0; nt < 2; nt++) {
                int rbase = nt*8 + (lane & 3)*2;
#pragma unroll
                for (int e = 0; e < 4; e++) {
                    int s = s0 + ((e >> 1) << 3);
                    int ci = rbase + (e & 1);
                    float c = d_cos[s*16 + ci], sn = d_sin[s*16 + ci];
                    float xl = acc[mt][nt][e], xh = acc[mt][nt+2][e];
                    long long rb = (long long)(n*128 + s) * 512;
                    int col = h*32 + ci;
                    st_split(d_ga0_t, d_ga1_t, rb + col,      xl*c + xh*sn);
                    st_split(d_ga0_t, d_ga1_t, rb + col + 16, xh*c - xl*sn);
                }
            }
        }
    } else {
        // G2: A = uT [r][t], B = qhT [s][t]; C2[r][s]
        u32 wbase = (u32)(warp - 4) * 32;
#pragma unroll
        for (int k0 = 0; k0 < 8; k0++) {
            u32 a[2][2][4];
#pragma unroll
            for (int sp = 0; sp < 2; sp++)
#pragma unroll
                for (int mt = 0; mt < 2; mt++)
                    ldm_x4(a[sp][mt], sbase + (sp ? UT1 : UT0)
                           + (mt*16 + (lane & 15))*272 + k0*32 + (lane >> 4)*16);
            u32 b[2][4][2];
#pragma unroll
            for (int sp = 0; sp < 2; sp++)
#pragma unroll
                for (int g = 0; g < 2; g++) {
                    u32 tr[4];
                    ldm_x4(tr, sbase + (sp ? QHT1 : QHT0)
                           + (wbase + g*16 + (lane & 15))*272 + k0*32 + (lane >> 4)*16);
                    b[sp][2*g][0] = tr[0];   b[sp][2*g][1] = tr[2];
                    b[sp][2*g+1][0] = tr[1]; b[sp][2*g+1][1] = tr[3];
                }
#pragma unroll
            for (int mt = 0; mt < 2; mt++)
#pragma unroll
                for (int nt = 0; nt < 4; nt++) {
                    mma_bf16(acc[mt][nt], a[0][mt], b[0][nt]);
                    mma_bf16(acc[mt][nt], a[0][mt], b[1][nt]);
                    mma_bf16(acc[mt][nt], a[1][mt], b[0][nt]);
                }
        }
#pragma unroll
        for (int nt = 0; nt < 4; nt++) {
            int sb = (int)wbase + nt*8 + (lane & 3)*2;
#pragma unroll
            for (int e = 0; e < 4; e++) {
                int s = sb + (e & 1);
                int r = (lane >> 2) + ((e >> 1) << 3);
                float c = d_cos[s*16 + r], sn = d_sin[s*16 + r];
                float yl = acc[0][nt][e], yh = acc[1][nt][e];
                long long rb = (long long)(n*128 + s) * 512;
                int col = 256 + h*32 + r;
                st_split(d_ga0_t, d_ga1_t, rb + col,      yl*c - yh*sn);
                st_split(d_ga0_t, d_ga1_t, rb + col + 16, yh*c + yl*sn);
            }
        }
    }
}

// ---------------- G chan (FFMA, small) --------------------------------------
__global__ __launch_bounds__(128) void k_gc() {
    __shared__ float Qn[32][34];
    __shared__ float Vs[32][34];
    __shared__ float Us[32][34];
    int nh = blockIdx.x;
    int n = nh >> 3, h = nh & 7;
    const float* qh = d_F_c + (long long)nh*1024;
    const float* vb = d_qvr_c + nh*1024;
    const float* ub = d_quo_c + nh*1024;
    int tid = threadIdx.x;
#pragma unroll
    for (int l = 0; l < 2; l++) {
        int lin = tid + l*128;
        int t = lin >> 3, sq = (lin & 7) << 2;
        float4 q = *(const float4*)(qh + t*32 + sq);
        Qn[t][sq] = q.x; Qn[t][sq+1] = q.y; Qn[t][sq+2] = q.z; Qn[t][sq+3] = q.w;
        float4 v = *(const float4*)(vb + t*32 + sq);
        Vs[t][sq] = v.x; Vs[t][sq+1] = v.y; Vs[t][sq+2] = v.z; Vs[t][sq+3] = v.w;
        float4 u = *(const float4*)(ub + t*32 + sq);
        Us[t][sq] = u.x; Us[t][sq+1] = u.y; Us[t][sq+2] = u.z; Us[t][sq+3] = u.w;
    }
    __syncthreads();
    int rg = tid & 7, sg = tid >> 3;
    float a1[2][4], a2[2][4];
#pragma unroll
    for (int i = 0; i < 2; i++)
#pragma unroll
        for (int j = 0; j < 4; j++) { a1[i][j] = 0.f; a2[i][j] = 0.f; }
#pragma unroll
    for (int t = 0; t < 32; t++) {
        float av[2], bv[2], vv[4], uv[4];
        av[0] = Qn[sg*2][t];
        av[1] = Qn[sg*2+1][t];
        float2 qb = *(const float2*)&Qn[t][sg*2];
        float2 v0 = *(const float2*)&Vs[t][rg*2];
        float2 v1 = *(const float2*)&Vs[t][rg*2+16];
        float2 u0 = *(const float2*)&Us[t][rg*2];
        float2 u1 = *(const float2*)&Us[t][rg*2+16];
        bv[0] = qb.x; bv[1] = qb.y;
        vv[0] = v0.x; vv[1] = v0.y; vv[2] = v1.x; vv[3] = v1.y;
        uv[0] = u0.x; uv[1] = u0.y; uv[2] = u1.x; uv[3] = u1.y;
#pragma unroll
        for (int si = 0; si < 2; si++)
#pragma unroll
            for (int rj = 0; rj < 4; rj++) {
                a1[si][rj] += av[si]*vv[rj];
                a2[si][rj] += bv[si]*uv[rj];
            }
    }
#pragma unroll
    for (int si = 0; si < 2; si++) {
        int s = sg*2 + si;
        long long rb = (long long)(n*32 + s) * 512;
#pragma unroll
        for (int rj = 0; rj < 2; rj++) {
            int r = rg*2 + rj;
            float c  = d_cos[s*16 + r];
            float sn = d_sin[s*16 + r];
            float xl = a1[si][rj], xh = a1[si][rj+2];
            float yl = a2[si][rj], yh = a2[si][rj+2];
            int col = h*32 + r;
            st_split(d_ga0_c, d_ga1_c, rb + col,        xl*c + xh*sn);
            st_split(d_ga0_c, d_ga1_c, rb + col + 16,   xh*c - xl*sn);
            st_split(d_ga0_c, d_ga1_c, rb + 256 + col,      yl*c - yh*sn);
            st_split(d_ga0_c, d_ga1_c, rb + 256 + col + 16, yh*c + yl*sn);
        }
    }
}

// ---------------- launch ---------------------------------------------------
extern "C" void kernel_launch(void* const* d_in, const int* in_sizes, int n_in,
                              void* d_out, int out_size)
{
    const float* qz = (const float*)d_in[0];
    const float* mask_t = (const float*)d_in[1];
    const float* mask_c = (const float*)d_in[2];
    const float* u_t = (const float*)d_in[3];
    const float* v_t = (const float*)d_in[4];
    const float* u_c = (const float*)d_in[5];
    const float* v_c = (const float*)d_in[6];
    float* out = (float*)d_out;

    cudaFuncSetAttribute(k_proj_mma, cudaFuncAttributeMaxDynamicSharedMemorySize, PROJ_SMEM);
    cudaFuncSetAttribute(k_final_mma, cudaFuncAttributeMaxDynamicSharedMemorySize, FIN_SMEM);
    cudaFuncSetAttribute(k_gt_mma, cudaFuncAttributeMaxDynamicSharedMemorySize, GT_SMEM);

    k_setup<<<8, 256>>>();
    k_split_qz<<<8192, 256>>>(qz);
    k_split_w<<<512, 256>>>(u_t, v_t, 0);
    k_split_w<<<512, 256>>>(u_c, v_c, 1);
    k_split_wf<<<512, 256>>>(u_t, v_t, 0);

    k_proj_mma<<<dim3(4, 256), 256, PROJ_SMEM>>>(0);   // launch idx 5 -> ncu captures this
    k_proj_mma<<<dim3(4, 256), 256, PROJ_SMEM>>>(1);

    k_ft<<<NT*HH, 256>>>(mask_t);
    k_fc<<<NC*HH, 256>>>(mask_c);

    k_softmax<<<32768, 256>>>();

    k_gt_mma<<<NT*HH, 256, GT_SMEM>>>();
    k_gc<<<NC*HH, 128>>>();

    k_split_wf<<<512, 256>>>(u_c, v_c, 1);
    k_final_mma<<<dim3(2, 256), 256, FIN_SMEM>>>(out, 0);
    k_final_mma<<<dim3(2, 256), 256, FIN_SMEM>>>(out + OUT_HALF, 1);
}

// round 13
// speedup vs baseline: 1.0430x; 1.0430x over previous
#include <cuda_runtime.h>
#include <cuda_bf16.h>

typedef unsigned int u32;
typedef unsigned long long u64;

// Problem constants
#define BB 8
#define CC 32
#define PP 128
#define DD 256
#define HH 8
#define RR 32
#define NT (BB*CC)
#define NC (BB*PP)
#define ROWS 32768
#define OUT_HALF (BB*CC*PP*DD)

// ---------------- scratch ----------------
__device__ __align__(256) float d_qur_t[NT*HH*PP*RR];
__device__ __align__(256) float d_quo_t[NT*HH*PP*RR];
__device__ __align__(256) float d_qvr_t[NT*HH*PP*RR];
__device__ __align__(256) float d_qur_c[NC*HH*CC*RR];
__device__ __align__(256) float d_quo_c[NC*HH*CC*RR];
__device__ __align__(256) float d_qvr_c[NC*HH*CC*RR];
__device__ __align__(256) float d_F_t[NT*HH*PP*PP];
__device__ __align__(256) float d_F_c[NC*HH*CC*CC];
__device__ __align__(256) float d_cos[PP*16];
__device__ __align__(256) float d_sin[PP*16];

__device__ __align__(256) __nv_bfloat16 d_qz0[ROWS*256];
__device__ __align__(256) __nv_bfloat16 d_qz1[ROWS*256];
__device__ __align__(256) __nv_bfloat16 d_qz2[ROWS*256];
__device__ __align__(256) __nv_bfloat16 d_wp_t[3][512*256];
__device__ __align__(256) __nv_bfloat16 d_wp_c[3][512*256];
__device__ __align__(256) __nv_bfloat16 d_wf_t[2][256*512];
__device__ __align__(256) __nv_bfloat16 d_wf_c[2][256*512];
__device__ __align__(256) __nv_bfloat16 d_ga0_t[ROWS*512];
__device__ __align__(256) __nv_bfloat16 d_ga1_t[ROWS*512];
__device__ __align__(256) __nv_bfloat16 d_ga0_c[ROWS*512];
__device__ __align__(256) __nv_bfloat16 d_ga1_c[ROWS*512];

// ---------------- HMMA + cp.async helpers (baseline PTX) -------------------
__device__ __forceinline__ void ldm_x4(u32* r, u32 addr) {
    asm volatile("ldmatrix.sync.aligned.m8n8.x4.shared.b16 {%0, %1, %2, %3}, [%4];" : "=r"(r[0]), "=r"(r[1]), "=r"(r[2]), "=r"(r[3]) : "r"(addr));
}
__device__ __forceinline__ void mma_bf16(float* d, const u32* a, const u32* b) {
    asm volatile("mma.sync.aligned.m16n8k16.row.col.f32.bf16.bf16.f32 {%0, %1, %2, %3}, {%4, %5, %6, %7}, {%8, %9}, {%0, %1, %2, %3};" : "+f"(d[0]), "+f"(d[1]), "+f"(d[2]), "+f"(d[3]) : "r"(a[0]), "r"(a[1]), "r"(a[2]), "r"(a[3]), "r"(b[0]), "r"(b[1]));
}
__device__ __forceinline__ void cpa(u32 s, const __nv_bfloat16* g) {
    asm volatile("cp.async.ca.shared.global [%0], [%1], 16;" :: "r"(s), "l"((u64)__cvta_generic_to_global((void*)g)) : "memory");
}
__device__ __forceinline__ void cpa_commit() { asm volatile("cp.async.commit_group;" ::: "memory"); }
__device__ __forceinline__ void cpa_wait0() { asm volatile("cp.async.wait_group 0;" ::: "memory"); }
__device__ __forceinline__ void cpa_wait1() { asm volatile("cp.async.wait_group 1;" ::: "memory"); }

#define TILE_BYTES 10240        // 128 rows * 80 bytes
#define PROJ_SMEM (2*6*TILE_BYTES)
#define FIN_SMEM  (2*4*TILE_BYTES)
#define FT_SMEM   67584         // 128*132*4 (aliases SuT/SvT staging)

__device__ __forceinline__ void st_split(__nv_bfloat16* A0, __nv_bfloat16* A1,
                                         long long i, float x) {
    __nv_bfloat16 b0 = __float2bfloat16(x);
    A0[i] = b0;
    A1[i] = __float2bfloat16(x - __bfloat162float(b0));
}

// ---------------- rope table ----------------
__global__ void k_setup() {
    int idx = blockIdx.x * blockDim.x + threadIdx.x;
    if (idx < PP*16) {
        int s = idx >> 4, i = idx & 15;
        double invf = pow(10000.0, -((double)(2*i)) / 32.0);
        double a = (double)s * invf;
        d_cos[idx] = (float)cos(a);
        d_sin[idx] = (float)sin(a);
    }
}

// ---------------- split qz into 3 bf16 components --------------------------
__global__ __launch_bounds__(256) void k_split_qz(const float* __restrict__ qz) {
    int i = (blockIdx.x * 256 + threadIdx.x) * 4;
    float4 x = *reinterpret_cast<const float4*>(qz + i);
    float xs[4];
    xs[0] = x.x; xs[1] = x.y; xs[2] = x.z; xs[3] = x.w;
    __align__(8) __nv_bfloat16 b0[4], b1[4], b2[4];
#pragma unroll
    for (int j = 0; j < 4; j++) {
        b0[j] = __float2bfloat16(xs[j]);
        float r = xs[j] - __bfloat162float(b0[j]);
        b1[j] = __float2bfloat16(r);
        b2[j] = __float2bfloat16(r - __bfloat162float(b1[j]));
    }
    *reinterpret_cast<uint2*>(&d_qz0[i]) = *reinterpret_cast<uint2*>(b0);
    *reinterpret_cast<uint2*>(&d_qz1[i]) = *reinterpret_cast<uint2*>(b1);
    *reinterpret_cast<uint2*>(&d_qz2[i]) = *reinterpret_cast<uint2*>(b2);
}

__global__ __launch_bounds__(256) void k_split_w(const float* __restrict__ U,
                                                 const float* __restrict__ V, int branch) {
    int idx = blockIdx.x * 256 + threadIdx.x;
    int n = idx >> 8, k = idx & 255;
    float x = (n < 256) ? U[n*256 + k] : V[(n-256)*256 + k];
    __nv_bfloat16* w0 = branch ? d_wp_c[0] : d_wp_t[0];
    __nv_bfloat16* w1 = branch ? d_wp_c[1] : d_wp_t[1];
    __nv_bfloat16* w2 = branch ? d_wp_c[2] : d_wp_t[2];
    __nv_bfloat16 b0 = __float2bfloat16(x);
    float r = x - __bfloat162float(b0);
    __nv_bfloat16 b1 = __float2bfloat16(r);
    w0[idx] = b0; w1[idx] = b1;
    w2[idx] = __float2bfloat16(r - __bfloat162float(b1));
}

__global__ __launch_bounds__(256) void k_split_wf(const float* __restrict__ U,
                                                  const float* __restrict__ V, int branch) {
    int idx = blockIdx.x * 256 + threadIdx.x;
    int n = idx >> 9, k = idx & 511;
    float x = (k < 256) ? U[k*256 + n] : V[(k-256)*256 + n];
    __nv_bfloat16* w0 = branch ? d_wf_c[0] : d_wf_t[0];
    __nv_bfloat16* w1 = branch ? d_wf_c[1] : d_wf_t[1];
    __nv_bfloat16 b0 = __float2bfloat16(x);
    w0[idx] = b0;
    w1[idx] = __float2bfloat16(x - __bfloat162float(b0));
}

// ---------------- proj GEMM (HMMA, cp.async pipeline, fused RoPE) ----------
__global__ __launch_bounds__(256, 1) void k_proj_mma(int branch) {
    extern __shared__ char smem[];
    const int tid = threadIdx.x;
    const u32 sbase = (u32)__cvta_generic_to_shared(smem);
    const int n0 = blockIdx.x * 128;
    const int m0 = blockIdx.y * 128;
    const int lane = tid & 31, warp = tid >> 5;
    const int wm = warp >> 1, wn = warp & 1;
    const __nv_bfloat16* W0 = branch ? d_wp_c[0] : d_wp_t[0];
    const __nv_bfloat16* W1 = branch ? d_wp_c[1] : d_wp_t[1];
    const __nv_bfloat16* W2 = branch ? d_wp_c[2] : d_wp_t[2];

    float acc[2][8][4];
#pragma unroll
    for (int mt = 0; mt < 2; mt++)
#pragma unroll
        for (int nt = 0; nt < 8; nt++)
#pragma unroll
            for (int e = 0; e < 4; e++) acc[mt][nt][e] = 0.f;

#pragma unroll 1
    for (int kc = -1; kc < 8; kc++) {
        int ld = kc + 1;
        if (ld < 8) {
            u32 stb = sbase + (u32)(ld & 1) * (6*TILE_BYTES);
#pragma unroll
            for (int t = 0; t < 12; t++) {
                int li = tid + t * 256;
                int seg = li & 3, row = (li >> 2) & 127, tile = li >> 9;
                const __nv_bfloat16* src;
                if (tile < 3) {
                    int grow = m0 + row;
                    if (branch) {
                        int b = grow >> 12, rem = grow & 4095;
                        grow = ((b << 5) + (rem & 31)) * 128 + (rem >> 5);
                    }
                    const __nv_bfloat16* A = (tile == 0) ? d_qz0 : (tile == 1) ? d_qz1 : d_qz2;
                    src = A + (long long)grow * 256 + ld * 32 + seg * 8;
                } else {
                    const __nv_bfloat16* W = (tile == 3) ? W0 : (tile == 4) ? W1 : W2;
                    src = W + (long long)(n0 + row) * 256 + ld * 32 + seg * 8;
                }
                cpa(stb + (u32)(tile * TILE_BYTES + row * 80 + seg * 16), src);
            }
            cpa_commit();
        }
        if (kc < 0) continue;
        if (kc < 7) cpa_wait1(); else cpa_wait0();
        __syncthreads();
        u32 stb = sbase + (u32)(kc & 1) * (6*TILE_BYTES);
#pragma unroll
        for (int ks = 0; ks < 2; ks++) {
            u32 afr[3][2][4];
#pragma unroll
            for (int sp = 0; sp < 3; sp++)
#pragma unroll
                for (int mt = 0; mt < 2; mt++) {
                    u32 addr = stb + sp * TILE_BYTES
                             + (wm * 32 + mt * 16 + (lane & 15)) * 80
                             + ks * 32 + (lane >> 4) * 16;
                    ldm_x4(afr[sp][mt], addr);
                }
#pragma unroll
            for (int sb = 0; sb < 3; sb++) {
                u32 bfr[8][2];
#pragma unroll
                for (int g = 0; g < 4; g++) {
                    u32 tr[4];
                    u32 addr = stb + (3 + sb) * TILE_BYTES
                             + (wn * 64 + g * 16 + (lane & 15)) * 80
                             + ks * 32 + (lane >> 4) * 16;
                    ldm_x4(tr, addr);
                    bfr[2*g][0] = tr[0];   bfr[2*g][1] = tr[2];
                    bfr[2*g+1][0] = tr[1]; bfr[2*g+1][1] = tr[3];
                }
                int na = 3 - sb;
#pragma unroll
                for (int sa = 0; sa < 3; sa++) {
                    if (sa < na) {
#pragma unroll
                        for (int mt = 0; mt < 2; mt++)
#pragma unroll
                            for (int nt = 0; nt < 8; nt++)
                                mma_bf16(acc[mt][nt], afr[sa][mt], bfr[nt]);
                    }
                }
            }
        }
        __syncthreads();
    }

    // fused RoPE epilogue
    float* OUR = branch ? d_qur_c : d_qur_t;
    float* OUO = branch ? d_quo_c : d_quo_t;
    float* OVR = branch ? d_qvr_c : d_qvr_t;
    const int Sbits = branch ? 5 : 7;
    const int Smask = (1 << Sbits) - 1;
    const int isQV = (n0 >= 256);
#pragma unroll
    for (int mt = 0; mt < 2; mt++) {
        int rA = m0 + wm * 32 + mt * 16 + (lane >> 2);
        int rB = rA + 8;
        int nA = rA >> Sbits, sA = rA & Smask;
        int nB = rB >> Sbits, sB = rB & Smask;
#pragma unroll
        for (int nt = 0; nt < 8; nt++) {
            int colh = (n0 & 255) + wn * 64 + nt * 8;
            int rr = (colh & 31) + (lane & 3) * 2;
            int h = (colh >> 5) & 7;
            float sgn = (rr < 16) ? -1.f : 1.f;
            int ci = rr & 15;
            float cA0 = d_cos[sA*16 + ci],     snA0 = d_sin[sA*16 + ci];
            float cA1 = d_cos[sA*16 + ci + 1], snA1 = d_sin[sA*16 + ci + 1];
            float cB0 = d_cos[sB*16 + ci],     snB0 = d_sin[sB*16 + ci];
            float cB1 = d_cos[sB*16 + ci + 1], snB1 = d_sin[sB*16 + ci + 1];
            float q0 = acc[mt][nt][0], q1 = acc[mt][nt][1];
            float q2 = acc[mt][nt][2], q3 = acc[mt][nt][3];
            float p0 = acc[mt][nt ^ 2][0], p1 = acc[mt][nt ^ 2][1];
            float p2 = acc[mt][nt ^ 2][2], p3 = acc[mt][nt ^ 2][3];
            long long baseA = (((long long)(nA * 8 + h) << Sbits) + sA) * 32 + rr;
            long long baseB = (((long long)(nB * 8 + h) << Sbits) + sB) * 32 + rr;
            if (!isQV) {
                float2 w;
                w.x = q0*cA0 + sgn*p0*snA0; w.y = q1*cA1 + sgn*p1*snA1;
                *reinterpret_cast<float2*>(&OUR[baseA]) = w;
                w.x = q0*cA0 - sgn*p0*snA0; w.y = q1*cA1 - sgn*p1*snA1;
                *reinterpret_cast<float2*>(&OUO[baseA]) = w;
                w.x = q2*cB0 + sgn*p2*snB0; w.y = q3*cB1 + sgn*p3*snB1;
                *reinterpret_cast<float2*>(&OUR[baseB]) = w;
                w.x = q2*cB0 - sgn*p2*snB0; w.y = q3*cB1 - sgn*p3*snB1;
                *reinterpret_cast<float2*>(&OUO[baseB]) = w;
            } else {
                float2 w;
                w.x = q0*cA0 + sgn*p0*snA0; w.y = q1*cA1 + sgn*p1*snA1;
                *reinterpret_cast<float2*>(&OVR[baseA]) = w;
                w.x = q2*cB0 + sgn*p2*snB0; w.y = q3*cB1 + sgn*p3*snB1;
                *reinterpret_cast<float2*>(&OVR[baseB]) = w;
            }
        }
    }
}

// ---------------- final GEMM (HMMA, cp.async pipeline) ---------------------
__global__ __launch_bounds__(256, 1) void k_final_mma(float* __restrict__ out, int branch) {
    extern __shared__ char smem[];
    const int tid = threadIdx.x;
    const u32 sbase = (u32)__cvta_generic_to_shared(smem);
    const int n0 = blockIdx.x * 128;
    const int m0 = blockIdx.y * 128;
    const int lane = tid & 31, warp = tid >> 5;
    const int wm = warp >> 1, wn = warp & 1;
    const __nv_bfloat16* G0 = branch ? d_ga0_c : d_ga0_t;
    const __nv_bfloat16* G1 = branch ? d_ga1_c : d_ga1_t;
    const __nv_bfloat16* F0 = branch ? d_wf_c[0] : d_wf_t[0];
    const __nv_bfloat16* F1 = branch ? d_wf_c[1] : d_wf_t[1];

    float acc[2][8][4];
#pragma unroll
    for (int mt = 0; mt < 2; mt++)
#pragma unroll
        for (int nt = 0; nt < 8; nt++)
#pragma unroll
            for (int e = 0; e < 4; e++) acc[mt][nt][e] = 0.f;

#pragma unroll 1
    for (int kc = -1; kc < 16; kc++) {
        int ld = kc + 1;
        if (ld < 16) {
            u32 stb = sbase + (u32)(ld & 1) * (4*TILE_BYTES);
#pragma unroll
            for (int t = 0; t < 8; t++) {
                int li = tid + t * 256;
                int seg = li & 3, row = (li >> 2) & 127, tile = li >> 9;
                const __nv_bfloat16* src;
                if (tile == 0)      src = G0 + (long long)(m0 + row) * 512 + ld * 32 + seg * 8;
                else if (tile == 1) src = G1 + (long long)(m0 + row) * 512 + ld * 32 + seg * 8;
                else if (tile == 2) src = F0 + (long long)(n0 + row) * 512 + ld * 32 + seg * 8;
                else                src = F1 + (long long)(n0 + row) * 512 + ld * 32 + seg * 8;
                cpa(stb + (u32)(tile * TILE_BYTES + row * 80 + seg * 16), src);
            }
            cpa_commit();
        }
        if (kc < 0) continue;
        if (kc < 15) cpa_wait1(); else cpa_wait0();
        __syncthreads();
        u32 stb = sbase + (u32)(kc & 1) * (4*TILE_BYTES);
#pragma unroll
        for (int ks = 0; ks < 2; ks++) {
            u32 afr[2][2][4];
#pragma unroll
            for (int sp = 0; sp < 2; sp++)
#pragma unroll
                for (int mt = 0; mt < 2; mt++) {
                    u32 addr = stb + sp * TILE_BYTES
                             + (wm * 32 + mt * 16 + (lane & 15)) * 80
                             + ks * 32 + (lane >> 4) * 16;
                    ldm_x4(afr[sp][mt], addr);
                }
#pragma unroll
            for (int sb = 0; sb < 2; sb++) {
                u32 bfr[8][2];
#pragma unroll
                for (int g = 0; g < 4; g++) {
                    u32 tr[4];
                    u32 addr = stb + (2 + sb) * TILE_BYTES
                             + (wn * 64 + g * 16 + (lane & 15)) * 80
                             + ks * 32 + (lane >> 4) * 16;
                    ldm_x4(tr, addr);
                    bfr[2*g][0] = tr[0];   bfr[2*g][1] = tr[2];
                    bfr[2*g+1][0] = tr[1]; bfr[2*g+1][1] = tr[3];
                }
                int na = 2 - sb;
#pragma unroll
                for (int sa = 0; sa < 2; sa++) {
                    if (sa < na) {
#pragma unroll
                        for (int mt = 0; mt < 2; mt++)
#pragma unroll
                            for (int nt = 0; nt < 8; nt++)
                                mma_bf16(acc[mt][nt], afr[sa][mt], bfr[nt]);
                    }
                }
            }
        }
        __syncthreads();
    }
#pragma unroll
    for (int mt = 0; mt < 2; mt++)
#pragma unroll
        for (int nt = 0; nt < 8; nt++) {
            int r = m0 + wm * 32 + mt * 16 + (lane >> 2);
            int c = n0 + wn * 64 + nt * 8 + (lane & 3) * 2;
            long long r0o, r1o;
            if (!branch) {
                r0o = (long long)r; r1o = (long long)(r + 8);
            } else {
                int nn = r >> 5, cc2 = r & 31;
                int b = nn >> 7, p = nn & 127;
                r0o = (long long)((b * 32 + cc2) * 128 + p);
                int r8 = r + 8;
                nn = r8 >> 5; cc2 = r8 & 31; b = nn >> 7; p = nn & 127;
                r1o = (long long)((b * 32 + cc2) * 128 + p);
            }
            float2 lo; lo.x = acc[mt][nt][0]; lo.y = acc[mt][nt][1];
            float2 hi; hi.x = acc[mt][nt][2]; hi.y = acc[mt][nt][3];
            *reinterpret_cast<float2*>(&out[r0o * 256 + c]) = lo;
            *reinterpret_cast<float2*>(&out[r1o * 256 + c]) = hi;
        }
}

// ---------------- F_t + fused joint softmax --------------------------------
// Phase 1: F tile = qur@qvr^T + mask (FFMA, tile kept in smem)
// Phase 2: warp-per-row softmax over [128 time | 32 chan] candidates;
//          writes qh_t to d_F_t and qh_c in place to d_F_c.
__global__ __launch_bounds__(256) void k_ft(const float* __restrict__ mask) {
    extern __shared__ float sft[];
    float* SuT = sft;                 // [32][132] during phase 1
    float* SvT = sft + 32*132;
    float* Ftile = sft;               // [128][132] after compute (aliases)
    int nh = blockIdx.x;
    int n = nh >> 3, h = nh & 7;
    const float* ubase = d_qur_t + nh*128*32;
    const float* vbase = d_qvr_t + nh*128*32;
    int tid = threadIdx.x;
#pragma unroll
    for (int l = 0; l < 4; l++) {
        int lin = tid + l*256;
        int s = lin >> 3, rq = (lin & 7) << 2;
        float4 u = *reinterpret_cast<const float4*>(ubase + s*32 + rq);
        SuT[rq*132 + s] = u.x; SuT[(rq+1)*132 + s] = u.y;
        SuT[(rq+2)*132 + s] = u.z; SuT[(rq+3)*132 + s] = u.w;
        float4 v = *reinterpret_cast<const float4*>(vbase + s*32 + rq);
        SvT[rq*132 + s] = v.x; SvT[(rq+1)*132 + s] = v.y;
        SvT[(rq+2)*132 + s] = v.z; SvT[(rq+3)*132 + s] = v.w;
    }
    __syncthreads();
    int tx = tid & 15, ty = tid >> 4;
    float acc[8][8];
#pragma unroll
    for (int i = 0; i < 8; i++)
#pragma unroll
        for (int j = 0; j < 8; j++) acc[i][j] = 0.f;
#pragma unroll
    for (int k = 0; k < 32; k++) {
        float a[8], b[8];
        *(float4*)&a[0] = *(const float4*)&SuT[k*132 + ty*8];
        *(float4*)&a[4] = *(const float4*)&SuT[k*132 + ty*8+4];
        *(float4*)&b[0] = *(const float4*)&SvT[k*132 + tx*8];
        *(float4*)&b[4] = *(const float4*)&SvT[k*132 + tx*8+4];
#pragma unroll
        for (int i = 0; i < 8; i++)
#pragma unroll
            for (int j = 0; j < 8; j++) acc[i][j] += a[i]*b[j];
    }
    __syncthreads();   // all reads of SuT/SvT done; reuse region as Ftile
    const float* mrow = mask + (long long)n*16384;
#pragma unroll
    for (int i = 0; i < 8; i++) {
        int s = ty*8 + i;
#pragma unroll
        for (int j4 = 0; j4 < 2; j4++) {
            int t = tx*8 + j4*4;
            float4 m4 = *reinterpret_cast<const float4*>(mrow + s*128 + t);
            float4 o;
            o.x = acc[i][j4*4]   + m4.x;
            o.y = acc[i][j4*4+1] + m4.y;
            o.z = acc[i][j4*4+2] + m4.z;
            o.w = acc[i][j4*4+3] + m4.w;
            *reinterpret_cast<float4*>(&Ftile[s*132 + t]) = o;
        }
    }
    __syncthreads();
    // phase 2: softmax, warp w handles rows w*16 .. w*16+15
    int warp = tid >> 5, lane = tid & 31;
    int b = n >> 5, c = n & 31;
    float* ftout_base = d_F_t + (long long)nh*16384;
#pragma unroll 1
    for (int i = 0; i < 16; i++) {
        int p = warp*16 + i;
        float* fc = d_F_c + ((long long)(((b*128 + p)*8 + h)*32 + c))*32;
        float v[5];
        v[0] = Ftile[p*132 + lane];
        v[1] = Ftile[p*132 + lane + 32];
        v[2] = Ftile[p*132 + lane + 64];
        v[3] = Ftile[p*132 + lane + 96];
        v[4] = fc[lane];
        float m = v[0];
#pragma unroll
        for (int q = 1; q < 5; q++) m = fmaxf(m, v[q]);
#pragma unroll
        for (int off = 16; off >= 1; off >>= 1)
            m = fmaxf(m, __shfl_xor_sync(0xffffffffu, m, off));
        float sum = 0.f;
#pragma unroll
        for (int q = 0; q < 5; q++) { v[q] = expf(256.f*(v[q] - m)); sum += v[q]; }
#pragma unroll
        for (int off = 16; off >= 1; off >>= 1)
            sum += __shfl_xor_sync(0xffffffffu, sum, off);
        float inv = 1.f / sum;
        float* ftout = ftout_base + p*128;
        ftout[lane]      = v[0]*inv;
        ftout[lane+32]   = v[1]*inv;
        ftout[lane+64]   = v[2]*inv;
        ftout[lane+96]   = v[3]*inv;
        fc[lane]         = v[4]*inv;
    }
}

// ---------------- F_c (raw logits + mask) -----------------------------------
__global__ __launch_bounds__(256) void k_fc(const float* __restrict__ mask) {
    __shared__ float SuT[32][36];
    __shared__ float SvT[32][36];
    int nh = blockIdx.x;
    int n = nh >> 3;
    const float* ubase = d_qur_c + nh*1024;
    const float* vbase = d_qvr_c + nh*1024;
    int tid = threadIdx.x;
    {
        int s = tid >> 3, rq = (tid & 7) << 2;
        float4 u = *reinterpret_cast<const float4*>(ubase + s*32 + rq);
        SuT[rq][s] = u.x; SuT[rq+1][s] = u.y; SuT[rq+2][s] = u.z; SuT[rq+3][s] = u.w;
        float4 v = *reinterpret_cast<const float4*>(vbase + s*32 + rq);
        SvT[rq][s] = v.x; SvT[rq+1][s] = v.y; SvT[rq+2][s] = v.z; SvT[rq+3][s] = v.w;
    }
    __syncthreads();
    int tx = tid & 7, ty = tid >> 3;
    float acc[4];
    acc[0] = 0.f; acc[1] = 0.f; acc[2] = 0.f; acc[3] = 0.f;
#pragma unroll
    for (int k = 0; k < 32; k++) {
        float a = SuT[k][ty];
        float4 b = *(const float4*)&SvT[k][tx*4];
        acc[0] += a*b.x; acc[1] += a*b.y; acc[2] += a*b.z; acc[3] += a*b.w;
    }
    int t0 = tx*4;
    float4 m4 = *reinterpret_cast<const float4*>(mask + (long long)n*1024 + ty*32 + t0);
    float4 o;
    o.x = acc[0] + m4.x; o.y = acc[1] + m4.y; o.z = acc[2] + m4.z; o.w = acc[3] + m4.w;
    *reinterpret_cast<float4*>(d_F_c + (long long)nh*1024 + ty*32 + t0) = o;
}

// ---------------- G time (FFMA, verified R10 version) -----------------------
__global__ __launch_bounds__(256) void k_gt() {
    __shared__ float Qa[32][132];
    __shared__ float Qb[32][132];
    __shared__ float Vs[32][34];
    __shared__ float Us[32][34];
    int nh = blockIdx.x;
    int n = nh >> 3, h = nh & 7;
    const float* qh = d_F_t + (long long)nh*16384;
    const float* vb = d_qvr_t + nh*4096;
    const float* ub = d_quo_t + nh*4096;
    int tid = threadIdx.x;
    int rg = tid & 7, sg = tid >> 3;
    float a1[4][4], a2[4][4];
#pragma unroll
    for (int i = 0; i < 4; i++)
#pragma unroll
        for (int j = 0; j < 4; j++) { a1[i][j] = 0.f; a2[i][j] = 0.f; }

    for (int t0 = 0; t0 < 128; t0 += 32) {
        __syncthreads();
#pragma unroll
        for (int l = 0; l < 4; l++) {
            int lin = tid + l*256;
            int s = lin >> 3, iq = (lin & 7) << 2;
            float4 q = *(const float4*)(qh + s*128 + t0 + iq);
            Qa[iq][s] = q.x; Qa[iq+1][s] = q.y; Qa[iq+2][s] = q.z; Qa[iq+3][s] = q.w;
        }
#pragma unroll
        for (int l = 0; l < 4; l++) {
            int lin = tid + l*256;
            int i = lin >> 5, sq = (lin & 31) << 2;
            float4 q = *(const float4*)(qh + (t0 + i)*128 + sq);
            *(float4*)&Qb[i][sq] = q;
        }
        {
            int i = tid >> 3, rq = (tid & 7) << 2;
            float4 v = *(const float4*)(vb + (t0 + i)*32 + rq);
            Vs[i][rq] = v.x; Vs[i][rq+1] = v.y; Vs[i][rq+2] = v.z; Vs[i][rq+3] = v.w;
            float4 u = *(const float4*)(ub + (t0 + i)*32 + rq);
            Us[i][rq] = u.x; Us[i][rq+1] = u.y; Us[i][rq+2] = u.z; Us[i][rq+3] = u.w;
        }
        __syncthreads();
#pragma unroll
        for (int i = 0; i < 32; i++) {
            float4 qa = *(const float4*)&Qa[i][sg*4];
            float4 qb = *(const float4*)&Qb[i][sg*4];
            float2 v0 = *(const float2*)&Vs[i][rg*2];
            float2 v1 = *(const float2*)&Vs[i][rg*2+16];
            float2 u0 = *(const float2*)&Us[i][rg*2];
            float2 u1 = *(const float2*)&Us[i][rg*2+16];
            float av[4], bv[4], vv[4], uv[4];
            av[0] = qa.x; av[1] = qa.y; av[2] = qa.z; av[3] = qa.w;
            bv[0] = qb.x; bv[1] = qb.y; bv[2] = qb.z; bv[3] = qb.w;
            vv[0] = v0.x; vv[1] = v0.y; vv[2] = v1.x; vv[3] = v1.y;
            uv[0] = u0.x; uv[1] = u0.y; uv[2] = u1.x; uv[3] = u1.y;
#pragma unroll
            for (int si = 0; si < 4; si++)
#pragma unroll
                for (int rj = 0; rj < 4; rj++) {
                    a1[si][rj] += av[si]*vv[rj];
                    a2[si][rj] += bv[si]*uv[rj];
                }
        }
    }
#pragma unroll
    for (int si = 0; si < 4; si++) {
        int s = sg*4 + si;
        long long rb = (long long)(n*128 + s) * 512;
#pragma unroll
        for (int rj = 0; rj < 2; rj++) {
            int r = rg*2 + rj;
            float c  = d_cos[s*16 + r];
            float sn = d_sin[s*16 + r];
            float xl = a1[si][rj], xh = a1[si][rj+2];
            float yl = a2[si][rj], yh = a2[si][rj+2];
            int col = h*32 + r;
            st_split(d_ga0_t, d_ga1_t, rb + col,        xl*c + xh*sn);
            st_split(d_ga0_t, d_ga1_t, rb + col + 16,   xh*c - xl*sn);
            st_split(d_ga0_t, d_ga1_t, rb + 256 + col,      yl*c - yh*sn);
            st_split(d_ga0_t, d_ga1_t, rb + 256 + col + 16, yh*c + yl*sn);
        }
    }
}

// ---------------- G chan (FFMA, small) --------------------------------------
__global__ __launch_bounds__(128) void k_gc() {
    __shared__ float Qn[32][34];
    __shared__ float Vs[32][34];
    __shared__ float Us[32][34];
    int nh = blockIdx.x;
    int n = nh >> 3, h = nh & 7;
    const float* qh = d_F_c + (long long)nh*1024;
    const float* vb = d_qvr_c + nh*1024;
    const float* ub = d_quo_c + nh*1024;
    int tid = threadIdx.x;
#pragma unroll
    for (int l = 0; l < 2; l++) {
        int lin = tid + l*128;
        int t = lin >> 3, sq = (lin & 7) << 2;
        float4 q = *(const float4*)(qh + t*32 + sq);
        Qn[t][sq] = q.x; Qn[t][sq+1] = q.y; Qn[t][sq+2] = q.z; Qn[t][sq+3] = q.w;
        float4 v = *(const float4*)(vb + t*32 + sq);
        Vs[t][sq] = v.x; Vs[t][sq+1] = v.y; Vs[t][sq+2] = v.z; Vs[t][sq+3] = v.w;
        float4 u = *(const float4*)(ub + t*32 + sq);
        Us[t][sq] = u.x; Us[t][sq+1] = u.y; Us[t][sq+2] = u.z; Us[t][sq+3] = u.w;
    }
    __syncthreads();
    int rg = tid & 7, sg = tid >> 3;
    float a1[2][4], a2[2][4];
#pragma unroll
    for (int i = 0; i < 2; i++)
#pragma unroll
        for (int j = 0; j < 4; j++) { a1[i][j] = 0.f; a2[i][j] = 0.f; }
#pragma unroll
    for (int t = 0; t < 32; t++) {
        float av[2], bv[2], vv[4], uv[4];
        av[0] = Qn[sg*2][t];
        av[1] = Qn[sg*2+1][t];
        float2 qb = *(const float2*)&Qn[t][sg*2];
        float2 v0 = *(const float2*)&Vs[t][rg*2];
        float2 v1 = *(const float2*)&Vs[t][rg*2+16];
        float2 u0 = *(const float2*)&Us[t][rg*2];
        float2 u1 = *(const float2*)&Us[t][rg*2+16];
        bv[0] = qb.x; bv[1] = qb.y;
        vv[0] = v0.x; vv[1] = v0.y; vv[2] = v1.x; vv[3] = v1.y;
        uv[0] = u0.x; uv[1] = u0.y; uv[2] = u1.x; uv[3] = u1.y;
#pragma unroll
        for (int si = 0; si < 2; si++)
#pragma unroll
            for (int rj = 0; rj < 4; rj++) {
                a1[si][rj] += av[si]*vv[rj];
                a2[si][rj] += bv[si]*uv[rj];
            }
    }
#pragma unroll
    for (int si = 0; si < 2; si++) {
        int s = sg*2 + si;
        long long rb = (long long)(n*32 + s) * 512;
#pragma unroll
        for (int rj = 0; rj < 2; rj++) {
            int r = rg*2 + rj;
            float c  = d_cos[s*16 + r];
            float sn = d_sin[s*16 + r];
            float xl = a1[si][rj], xh = a1[si][rj+2];
            float yl = a2[si][rj], yh = a2[si][rj+2];
            int col = h*32 + r;
            st_split(d_ga0_c, d_ga1_c, rb + col,        xl*c + xh*sn);
            st_split(d_ga0_c, d_ga1_c, rb + col + 16,   xh*c - xl*sn);
            st_split(d_ga0_c, d_ga1_c, rb + 256 + col,      yl*c - yh*sn);
            st_split(d_ga0_c, d_ga1_c, rb + 256 + col + 16, yh*c + yl*sn);
        }
    }
}

// ---------------- launch ---------------------------------------------------
extern "C" void kernel_launch(void* const* d_in, const int* in_sizes, int n_in,
                              void* d_out, int out_size)
{
    const float* qz = (const float*)d_in[0];
    const float* mask_t = (const float*)d_in[1];
    const float* mask_c = (const float*)d_in[2];
    const float* u_t = (const float*)d_in[3];
    const float* v_t = (const float*)d_in[4];
    const float* u_c = (const float*)d_in[5];
    const float* v_c = (const float*)d_in[6];
    float* out = (float*)d_out;

    cudaFuncSetAttribute(k_proj_mma, cudaFuncAttributeMaxDynamicSharedMemorySize, PROJ_SMEM);
    cudaFuncSetAttribute(k_final_mma, cudaFuncAttributeMaxDynamicSharedMemorySize, FIN_SMEM);
    cudaFuncSetAttribute(k_ft, cudaFuncAttributeMaxDynamicSharedMemorySize, FT_SMEM);

    k_setup<<<8, 256>>>();
    k_split_qz<<<8192, 256>>>(qz);
    k_split_w<<<512, 256>>>(u_t, v_t, 0);
    k_split_w<<<512, 256>>>(u_c, v_c, 1);
    k_split_wf<<<512, 256>>>(u_t, v_t, 0);

    k_proj_mma<<<dim3(4, 256), 256, PROJ_SMEM>>>(0);
    k_proj_mma<<<dim3(4, 256), 256, PROJ_SMEM>>>(1);

    k_fc<<<NC*HH, 256>>>(mask_c);            // raw F_c logits first
    k_ft<<<NT*HH, 256, FT_SMEM>>>(mask_t);   // F_t + fused joint softmax

    k_gt<<<NT*HH, 256>>>();
    k_gc<<<NC*HH, 128>>>();

    k_split_wf<<<512, 256>>>(u_c, v_c, 1);
    k_final_mma<<<dim3(2, 256), 256, FIN_SMEM>>>(out, 0);
    k_final_mma<<<dim3(2, 256), 256, FIN_SMEM>>>(out + OUT_HALF, 1);
}

// round 14
// speedup vs baseline: 1.1296x; 1.0831x over previous
#include <cuda_runtime.h>
#include <cuda_bf16.h>

typedef unsigned int u32;
typedef unsigned long long u64;

// Problem constants
#define BB 8
#define CC 32
#define PP 128
#define DD 256
#define HH 8
#define RR 32
#define NT (BB*CC)
#define NC (BB*PP)
#define ROWS 32768
#define OUT_HALF (BB*CC*PP*DD)

// ---------------- scratch ----------------
__device__ __align__(256) float d_qur_t[NT*HH*PP*RR];
__device__ __align__(256) float d_quo_t[NT*HH*PP*RR];
__device__ __align__(256) float d_qvr_t[NT*HH*PP*RR];
__device__ __align__(256) float d_qur_c[NC*HH*CC*RR];
__device__ __align__(256) float d_quo_c[NC*HH*CC*RR];
__device__ __align__(256) float d_qvr_c[NC*HH*CC*RR];
__device__ __align__(256) float d_F_t[NT*HH*PP*PP];
__device__ __align__(256) float d_F_c[NC*HH*CC*CC];
__device__ __align__(256) float d_cos[PP*16];
__device__ __align__(256) float d_sin[PP*16];

__device__ __align__(256) __nv_bfloat16 d_qz0[ROWS*256];
__device__ __align__(256) __nv_bfloat16 d_qz1[ROWS*256];
__device__ __align__(256) __nv_bfloat16 d_qz2[ROWS*256];
__device__ __align__(256) __nv_bfloat16 d_wp_t[3][512*256];
__device__ __align__(256) __nv_bfloat16 d_wp_c[3][512*256];
__device__ __align__(256) __nv_bfloat16 d_wf_t[2][256*512];
__device__ __align__(256) __nv_bfloat16 d_wf_c[2][256*512];
__device__ __align__(256) __nv_bfloat16 d_ga0_t[ROWS*512];
__device__ __align__(256) __nv_bfloat16 d_ga1_t[ROWS*512];
__device__ __align__(256) __nv_bfloat16 d_ga0_c[ROWS*512];
__device__ __align__(256) __nv_bfloat16 d_ga1_c[ROWS*512];

// ---------------- HMMA + cp.async helpers (baseline PTX) -------------------
__device__ __forceinline__ void ldm_x4(u32* r, u32 addr) {
    asm volatile("ldmatrix.sync.aligned.m8n8.x4.shared.b16 {%0, %1, %2, %3}, [%4];" : "=r"(r[0]), "=r"(r[1]), "=r"(r[2]), "=r"(r[3]) : "r"(addr));
}
__device__ __forceinline__ void ldm_x4_t(u32* r, u32 addr) {
    asm volatile("ldmatrix.sync.aligned.m8n8.x4.trans.shared.b16 {%0, %1, %2, %3}, [%4];" : "=r"(r[0]), "=r"(r[1]), "=r"(r[2]), "=r"(r[3]) : "r"(addr));
}
__device__ __forceinline__ void mma_bf16(float* d, const u32* a, const u32* b) {
    asm volatile("mma.sync.aligned.m16n8k16.row.col.f32.bf16.bf16.f32 {%0, %1, %2, %3}, {%4, %5, %6, %7}, {%8, %9}, {%0, %1, %2, %3};" : "+f"(d[0]), "+f"(d[1]), "+f"(d[2]), "+f"(d[3]) : "r"(a[0]), "r"(a[1]), "r"(a[2]), "r"(a[3]), "r"(b[0]), "r"(b[1]));
}
__device__ __forceinline__ void cpa(u32 s, const __nv_bfloat16* g) {
    asm volatile("cp.async.ca.shared.global [%0], [%1], 16;" :: "r"(s), "l"((u64)__cvta_generic_to_global((void*)g)) : "memory");
}
__device__ __forceinline__ void cpa_commit() { asm volatile("cp.async.commit_group;" ::: "memory"); }
__device__ __forceinline__ void cpa_wait0() { asm volatile("cp.async.wait_group 0;" ::: "memory"); }
__device__ __forceinline__ void cpa_wait1() { asm volatile("cp.async.wait_group 1;" ::: "memory"); }

#define TILE_BYTES 10240        // 128 rows * 80 bytes
#define PROJ_SMEM (2*6*TILE_BYTES)
#define FIN_SMEM  (2*4*TILE_BYTES)

// k_gt_mma v3 smem: natural layouts only (stride 272B for QH, 80B for V/U)
#define GQH0 0
#define GQH1 34816
#define GV0  69632
#define GV1  79872
#define GU0  90112
#define GU1  100352
#define GT_SMEM 110592

__device__ __forceinline__ void st_split(__nv_bfloat16* A0, __nv_bfloat16* A1,
                                         long long i, float x) {
    __nv_bfloat16 b0 = __float2bfloat16(x);
    A0[i] = b0;
    A1[i] = __float2bfloat16(x - __bfloat162float(b0));
}

// ---------------- rope table ----------------
__global__ void k_setup() {
    int idx = blockIdx.x * blockDim.x + threadIdx.x;
    if (idx < PP*16) {
        int s = idx >> 4, i = idx & 15;
        double invf = pow(10000.0, -((double)(2*i)) / 32.0);
        double a = (double)s * invf;
        d_cos[idx] = (float)cos(a);
        d_sin[idx] = (float)sin(a);
    }
}

// ---------------- split qz into 3 bf16 components --------------------------
__global__ __launch_bounds__(256) void k_split_qz(const float* __restrict__ qz) {
    int i = (blockIdx.x * 256 + threadIdx.x) * 4;
    float4 x = *reinterpret_cast<const float4*>(qz + i);
    float xs[4];
    xs[0] = x.x; xs[1] = x.y; xs[2] = x.z; xs[3] = x.w;
    __align__(8) __nv_bfloat16 b0[4], b1[4], b2[4];
#pragma unroll
    for (int j = 0; j < 4; j++) {
        b0[j] = __float2bfloat16(xs[j]);
        float r = xs[j] - __bfloat162float(b0[j]);
        b1[j] = __float2bfloat16(r);
        b2[j] = __float2bfloat16(r - __bfloat162float(b1[j]));
    }
    *reinterpret_cast<uint2*>(&d_qz0[i]) = *reinterpret_cast<uint2*>(b0);
    *reinterpret_cast<uint2*>(&d_qz1[i]) = *reinterpret_cast<uint2*>(b1);
    *reinterpret_cast<uint2*>(&d_qz2[i]) = *reinterpret_cast<uint2*>(b2);
}

__global__ __launch_bounds__(256) void k_split_w(const float* __restrict__ U,
                                                 const float* __restrict__ V, int branch) {
    int idx = blockIdx.x * 256 + threadIdx.x;
    int n = idx >> 8, k = idx & 255;
    float x = (n < 256) ? U[n*256 + k] : V[(n-256)*256 + k];
    __nv_bfloat16* w0 = branch ? d_wp_c[0] : d_wp_t[0];
    __nv_bfloat16* w1 = branch ? d_wp_c[1] : d_wp_t[1];
    __nv_bfloat16* w2 = branch ? d_wp_c[2] : d_wp_t[2];
    __nv_bfloat16 b0 = __float2bfloat16(x);
    float r = x - __bfloat162float(b0);
    __nv_bfloat16 b1 = __float2bfloat16(r);
    w0[idx] = b0; w1[idx] = b1;
    w2[idx] = __float2bfloat16(r - __bfloat162float(b1));
}

__global__ __launch_bounds__(256) void k_split_wf(const float* __restrict__ U,
                                                  const float* __restrict__ V, int branch) {
    int idx = blockIdx.x * 256 + threadIdx.x;
    int n = idx >> 9, k = idx & 511;
    float x = (k < 256) ? U[k*256 + n] : V[(k-256)*256 + n];
    __nv_bfloat16* w0 = branch ? d_wf_c[0] : d_wf_t[0];
    __nv_bfloat16* w1 = branch ? d_wf_c[1] : d_wf_t[1];
    __nv_bfloat16 b0 = __float2bfloat16(x);
    w0[idx] = b0;
    w1[idx] = __float2bfloat16(x - __bfloat162float(b0));
}

// ---------------- proj GEMM (HMMA, cp.async pipeline, fused RoPE) ----------
__global__ __launch_bounds__(256, 1) void k_proj_mma(int branch) {
    extern __shared__ char smem[];
    const int tid = threadIdx.x;
    const u32 sbase = (u32)__cvta_generic_to_shared(smem);
    const int n0 = blockIdx.x * 128;
    const int m0 = blockIdx.y * 128;
    const int lane = tid & 31, warp = tid >> 5;
    const int wm = warp >> 1, wn = warp & 1;
    const __nv_bfloat16* W0 = branch ? d_wp_c[0] : d_wp_t[0];
    const __nv_bfloat16* W1 = branch ? d_wp_c[1] : d_wp_t[1];
    const __nv_bfloat16* W2 = branch ? d_wp_c[2] : d_wp_t[2];

    float acc[2][8][4];
#pragma unroll
    for (int mt = 0; mt < 2; mt++)
#pragma unroll
        for (int nt = 0; nt < 8; nt++)
#pragma unroll
            for (int e = 0; e < 4; e++) acc[mt][nt][e] = 0.f;

#pragma unroll 1
    for (int kc = -1; kc < 8; kc++) {
        int ld = kc + 1;
        if (ld < 8) {
            u32 stb = sbase + (u32)(ld & 1) * (6*TILE_BYTES);
#pragma unroll
            for (int t = 0; t < 12; t++) {
                int li = tid + t * 256;
                int seg = li & 3, row = (li >> 2) & 127, tile = li >> 9;
                const __nv_bfloat16* src;
                if (tile < 3) {
                    int grow = m0 + row;
                    if (branch) {
                        int b = grow >> 12, rem = grow & 4095;
                        grow = ((b << 5) + (rem & 31)) * 128 + (rem >> 5);
                    }
                    const __nv_bfloat16* A = (tile == 0) ? d_qz0 : (tile == 1) ? d_qz1 : d_qz2;
                    src = A + (long long)grow * 256 + ld * 32 + seg * 8;
                } else {
                    const __nv_bfloat16* W = (tile == 3) ? W0 : (tile == 4) ? W1 : W2;
                    src = W + (long long)(n0 + row) * 256 + ld * 32 + seg * 8;
                }
                cpa(stb + (u32)(tile * TILE_BYTES + row * 80 + seg * 16), src);
            }
            cpa_commit();
        }
        if (kc < 0) continue;
        if (kc < 7) cpa_wait1(); else cpa_wait0();
        __syncthreads();
        u32 stb = sbase + (u32)(kc & 1) * (6*TILE_BYTES);
#pragma unroll
        for (int ks = 0; ks < 2; ks++) {
            u32 afr[3][2][4];
#pragma unroll
            for (int sp = 0; sp < 3; sp++)
#pragma unroll
                for (int mt = 0; mt < 2; mt++) {
                    u32 addr = stb + sp * TILE_BYTES
                             + (wm * 32 + mt * 16 + (lane & 15)) * 80
                             + ks * 32 + (lane >> 4) * 16;
                    ldm_x4(afr[sp][mt], addr);
                }
#pragma unroll
            for (int sb = 0; sb < 3; sb++) {
                u32 bfr[8][2];
#pragma unroll
                for (int g = 0; g < 4; g++) {
                    u32 tr[4];
                    u32 addr = stb + (3 + sb) * TILE_BYTES
                             + (wn * 64 + g * 16 + (lane & 15)) * 80
                             + ks * 32 + (lane >> 4) * 16;
                    ldm_x4(tr, addr);
                    bfr[2*g][0] = tr[0];   bfr[2*g][1] = tr[2];
                    bfr[2*g+1][0] = tr[1]; bfr[2*g+1][1] = tr[3];
                }
                int na = 3 - sb;
#pragma unroll
                for (int sa = 0; sa < 3; sa++) {
                    if (sa < na) {
#pragma unroll
                        for (int mt = 0; mt < 2; mt++)
#pragma unroll
                            for (int nt = 0; nt < 8; nt++)
                                mma_bf16(acc[mt][nt], afr[sa][mt], bfr[nt]);
                    }
                }
            }
        }
        __syncthreads();
    }

    // fused RoPE epilogue
    float* OUR = branch ? d_qur_c : d_qur_t;
    float* OUO = branch ? d_quo_c : d_quo_t;
    float* OVR = branch ? d_qvr_c : d_qvr_t;
    const int Sbits = branch ? 5 : 7;
    const int Smask = (1 << Sbits) - 1;
    const int isQV = (n0 >= 256);
#pragma unroll
    for (int mt = 0; mt < 2; mt++) {
        int rA = m0 + wm * 32 + mt * 16 + (lane >> 2);
        int rB = rA + 8;
        int nA = rA >> Sbits, sA = rA & Smask;
        int nB = rB >> Sbits, sB = rB & Smask;
#pragma unroll
        for (int nt = 0; nt < 8; nt++) {
            int colh = (n0 & 255) + wn * 64 + nt * 8;
            int rr = (colh & 31) + (lane & 3) * 2;
            int h = (colh >> 5) & 7;
            float sgn = (rr < 16) ? -1.f : 1.f;
            int ci = rr & 15;
            float cA0 = d_cos[sA*16 + ci],     snA0 = d_sin[sA*16 + ci];
            float cA1 = d_cos[sA*16 + ci + 1], snA1 = d_sin[sA*16 + ci + 1];
            float cB0 = d_cos[sB*16 + ci],     snB0 = d_sin[sB*16 + ci];
            float cB1 = d_cos[sB*16 + ci + 1], snB1 = d_sin[sB*16 + ci + 1];
            float q0 = acc[mt][nt][0], q1 = acc[mt][nt][1];
            float q2 = acc[mt][nt][2], q3 = acc[mt][nt][3];
            float p0 = acc[mt][nt ^ 2][0], p1 = acc[mt][nt ^ 2][1];
            float p2 = acc[mt][nt ^ 2][2], p3 = acc[mt][nt ^ 2][3];
            long long baseA = (((long long)(nA * 8 + h) << Sbits) + sA) * 32 + rr;
            long long baseB = (((long long)(nB * 8 + h) << Sbits) + sB) * 32 + rr;
            if (!isQV) {
                float2 w;
                w.x = q0*cA0 + sgn*p0*snA0; w.y = q1*cA1 + sgn*p1*snA1;
                *reinterpret_cast<float2*>(&OUR[baseA]) = w;
                w.x = q0*cA0 - sgn*p0*snA0; w.y = q1*cA1 - sgn*p1*snA1;
                *reinterpret_cast<float2*>(&OUO[baseA]) = w;
                w.x = q2*cB0 + sgn*p2*snB0; w.y = q3*cB1 + sgn*p3*snB1;
                *reinterpret_cast<float2*>(&OUR[baseB]) = w;
                w.x = q2*cB0 - sgn*p2*snB0; w.y = q3*cB1 - sgn*p3*snB1;
                *reinterpret_cast<float2*>(&OUO[baseB]) = w;
            } else {
                float2 w;
                w.x = q0*cA0 + sgn*p0*snA0; w.y = q1*cA1 + sgn*p1*snA1;
                *reinterpret_cast<float2*>(&OVR[baseA]) = w;
                w.x = q2*cB0 + sgn*p2*snB0; w.y = q3*cB1 + sgn*p3*snB1;
                *reinterpret_cast<float2*>(&OVR[baseB]) = w;
            }
        }
    }
}

// ---------------- final GEMM (HMMA, cp.async pipeline) ---------------------
__global__ __launch_bounds__(256, 1) void k_final_mma(float* __restrict__ out, int branch) {
    extern __shared__ char smem[];
    const int tid = threadIdx.x;
    const u32 sbase = (u32)__cvta_generic_to_shared(smem);
    const int n0 = blockIdx.x * 128;
    const int m0 = blockIdx.y * 128;
    const int lane = tid & 31, warp = tid >> 5;
    const int wm = warp >> 1, wn = warp & 1;
    const __nv_bfloat16* G0 = branch ? d_ga0_c : d_ga0_t;
    const __nv_bfloat16* G1 = branch ? d_ga1_c : d_ga1_t;
    const __nv_bfloat16* F0 = branch ? d_wf_c[0] : d_wf_t[0];
    const __nv_bfloat16* F1 = branch ? d_wf_c[1] : d_wf_t[1];

    float acc[2][8][4];
#pragma unroll
    for (int mt = 0; mt < 2; mt++)
#pragma unroll
        for (int nt = 0; nt < 8; nt++)
#pragma unroll
            for (int e = 0; e < 4; e++) acc[mt][nt][e] = 0.f;

#pragma unroll 1
    for (int kc = -1; kc < 16; kc++) {
        int ld = kc + 1;
        if (ld < 16) {
            u32 stb = sbase + (u32)(ld & 1) * (4*TILE_BYTES);
#pragma unroll
            for (int t = 0; t < 8; t++) {
                int li = tid + t * 256;
                int seg = li & 3, row = (li >> 2) & 127, tile = li >> 9;
                const __nv_bfloat16* src;
                if (tile == 0)      src = G0 + (long long)(m0 + row) * 512 + ld * 32 + seg * 8;
                else if (tile == 1) src = G1 + (long long)(m0 + row) * 512 + ld * 32 + seg * 8;
                else if (tile == 2) src = F0 + (long long)(n0 + row) * 512 + ld * 32 + seg * 8;
                else                src = F1 + (long long)(n0 + row) * 512 + ld * 32 + seg * 8;
                cpa(stb + (u32)(tile * TILE_BYTES + row * 80 + seg * 16), src);
            }
            cpa_commit();
        }
        if (kc < 0) continue;
        if (kc < 15) cpa_wait1(); else cpa_wait0();
        __syncthreads();
        u32 stb = sbase + (u32)(kc & 1) * (4*TILE_BYTES);
#pragma unroll
        for (int ks = 0; ks < 2; ks++) {
            u32 afr[2][2][4];
#pragma unroll
            for (int sp = 0; sp < 2; sp++)
#pragma unroll
                for (int mt = 0; mt < 2; mt++) {
                    u32 addr = stb + sp * TILE_BYTES
                             + (wm * 32 + mt * 16 + (lane & 15)) * 80
                             + ks * 32 + (lane >> 4) * 16;
                    ldm_x4(afr[sp][mt], addr);
                }
#pragma unroll
            for (int sb = 0; sb < 2; sb++) {
                u32 bfr[8][2];
#pragma unroll
                for (int g = 0; g < 4; g++) {
                    u32 tr[4];
                    u32 addr = stb + (2 + sb) * TILE_BYTES
                             + (wn * 64 + g * 16 + (lane & 15)) * 80
                             + ks * 32 + (lane >> 4) * 16;
                    ldm_x4(tr, addr);
                    bfr[2*g][0] = tr[0];   bfr[2*g][1] = tr[2];
                    bfr[2*g+1][0] = tr[1]; bfr[2*g+1][1] = tr[3];
                }
                int na = 2 - sb;
#pragma unroll
                for (int sa = 0; sa < 2; sa++) {
                    if (sa < na) {
#pragma unroll
                        for (int mt = 0; mt < 2; mt++)
#pragma unroll
                            for (int nt = 0; nt < 8; nt++)
                                mma_bf16(acc[mt][nt], afr[sa][mt], bfr[nt]);
                    }
                }
            }
        }
        __syncthreads();
    }
#pragma unroll
    for (int mt = 0; mt < 2; mt++)
#pragma unroll
        for (int nt = 0; nt < 8; nt++) {
            int r = m0 + wm * 32 + mt * 16 + (lane >> 2);
            int c = n0 + wn * 64 + nt * 8 + (lane & 3) * 2;
            long long r0o, r1o;
            if (!branch) {
                r0o = (long long)r; r1o = (long long)(r + 8);
            } else {
                int nn = r >> 5, cc2 = r & 31;
                int b = nn >> 7, p = nn & 127;
                r0o = (long long)((b * 32 + cc2) * 128 + p);
                int r8 = r + 8;
                nn = r8 >> 5; cc2 = r8 & 31; b = nn >> 7; p = nn & 127;
                r1o = (long long)((b * 32 + cc2) * 128 + p);
            }
            float2 lo; lo.x = acc[mt][nt][0]; lo.y = acc[mt][nt][1];
            float2 hi; hi.x = acc[mt][nt][2]; hi.y = acc[mt][nt][3];
            *reinterpret_cast<float2*>(&out[r0o * 256 + c]) = lo;
            *reinterpret_cast<float2*>(&out[r1o * 256 + c]) = hi;
        }
}

// ---------------- F_t (R10 version) -----------------------------------------
__global__ __launch_bounds__(256) void k_ft(const float* __restrict__ mask) {
    __shared__ float SuT[32][132];
    __shared__ float SvT[32][132];
    int nh = blockIdx.x;
    int n = nh >> 3;
    const float* ubase = d_qur_t + nh*128*32;
    const float* vbase = d_qvr_t + nh*128*32;
    int tid = threadIdx.x;
#pragma unroll
    for (int l = 0; l < 4; l++) {
        int lin = tid + l*256;
        int s = lin >> 3, rq = (lin & 7) << 2;
        float4 u = *reinterpret_cast<const float4*>(ubase + s*32 + rq);
        SuT[rq][s] = u.x; SuT[rq+1][s] = u.y; SuT[rq+2][s] = u.z; SuT[rq+3][s] = u.w;
        float4 v = *reinterpret_cast<const float4*>(vbase + s*32 + rq);
        SvT[rq][s] = v.x; SvT[rq+1][s] = v.y; SvT[rq+2][s] = v.z; SvT[rq+3][s] = v.w;
    }
    __syncthreads();
    int tx = tid & 15, ty = tid >> 4;
    float acc[8][8];
#pragma unroll
    for (int i = 0; i < 8; i++)
#pragma unroll
        for (int j = 0; j < 8; j++) acc[i][j] = 0.f;
#pragma unroll
    for (int k = 0; k < 32; k++) {
        float a[8], b[8];
        *(float4*)&a[0] = *(const float4*)&SuT[k][ty*8];
        *(float4*)&a[4] = *(const float4*)&SuT[k][ty*8+4];
        *(float4*)&b[0] = *(const float4*)&SvT[k][tx*8];
        *(float4*)&b[4] = *(const float4*)&SvT[k][tx*8+4];
#pragma unroll
        for (int i = 0; i < 8; i++)
#pragma unroll
            for (int j = 0; j < 8; j++) acc[i][j] += a[i]*b[j];
    }
    float* fout = d_F_t + (long long)nh*16384;
    const float* mrow = mask + (long long)n*16384;
#pragma unroll
    for (int i = 0; i < 8; i++) {
        int s = ty*8 + i;
#pragma unroll
        for (int j4 = 0; j4 < 2; j4++) {
            int t = tx*8 + j4*4;
            float4 m4 = *reinterpret_cast<const float4*>(mrow + s*128 + t);
            float4 o;
            o.x = acc[i][j4*4]   + m4.x;
            o.y = acc[i][j4*4+1] + m4.y;
            o.z = acc[i][j4*4+2] + m4.z;
            o.w = acc[i][j4*4+3] + m4.w;
            *reinterpret_cast<float4*>(fout + s*128 + t) = o;
        }
    }
}

// ---------------- F_c -------------------------------------------------------
__global__ __launch_bounds__(256) void k_fc(const float* __restrict__ mask) {
    __shared__ float SuT[32][36];
    __shared__ float SvT[32][36];
    int nh = blockIdx.x;
    int n = nh >> 3;
    const float* ubase = d_qur_c + nh*1024;
    const float* vbase = d_qvr_c + nh*1024;
    int tid = threadIdx.x;
    {
        int s = tid >> 3, rq = (tid & 7) << 2;
        float4 u = *reinterpret_cast<const float4*>(ubase + s*32 + rq);
        SuT[rq][s] = u.x; SuT[rq+1][s] = u.y; SuT[rq+2][s] = u.z; SuT[rq+3][s] = u.w;
        float4 v = *reinterpret_cast<const float4*>(vbase + s*32 + rq);
        SvT[rq][s] = v.x; SvT[rq+1][s] = v.y; SvT[rq+2][s] = v.z; SvT[rq+3][s] = v.w;
    }
    __syncthreads();
    int tx = tid & 7, ty = tid >> 3;
    float acc[4];
    acc[0] = 0.f; acc[1] = 0.f; acc[2] = 0.f; acc[3] = 0.f;
#pragma unroll
    for (int k = 0; k < 32; k++) {
        float a = SuT[k][ty];
        float4 b = *(const float4*)&SvT[k][tx*4];
        acc[0] += a*b.x; acc[1] += a*b.y; acc[2] += a*b.z; acc[3] += a*b.w;
    }
    int t0 = tx*4;
    float4 m4 = *reinterpret_cast<const float4*>(mask + (long long)n*1024 + ty*32 + t0);
    float4 o;
    o.x = acc[0] + m4.x; o.y = acc[1] + m4.y; o.z = acc[2] + m4.z; o.w = acc[3] + m4.w;
    *reinterpret_cast<float4*>(d_F_c + (long long)nh*1024 + ty*32 + t0) = o;
}

// ---------------- joint softmax (R10 version) -------------------------------
__global__ __launch_bounds__(256) void k_softmax() {
    int warp = threadIdx.x >> 5, lane = threadIdx.x & 31;
    int rowid = blockIdx.x * 8 + warp;
    int p  = rowid & 127;
    int r1 = rowid >> 7;
    int c  = r1 & 31;
    int r2 = r1 >> 5;
    int h  = r2 & 7;
    int b  = r2 >> 3;
    float* ft = d_F_t + ((long long)(((b*32 + c)*8 + h)*128 + p))*128;
    float* fc = d_F_c + ((long long)(((b*128 + p)*8 + h)*32 + c))*32;
    float v[5];
    v[0] = ft[lane]; v[1] = ft[lane+32]; v[2] = ft[lane+64]; v[3] = ft[lane+96];
    v[4] = fc[lane];
    float m = v[0];
#pragma unroll
    for (int i = 1; i < 5; i++) m = fmaxf(m, v[i]);
#pragma unroll
    for (int off = 16; off >= 1; off >>= 1)
        m = fmaxf(m, __shfl_xor_sync(0xffffffffu, m, off));
    float sum = 0.f;
#pragma unroll
    for (int i = 0; i < 5; i++) { v[i] = expf(256.f*(v[i] - m)); sum += v[i]; }
#pragma unroll
    for (int off = 16; off >= 1; off >>= 1)
        sum += __shfl_xor_sync(0xffffffffu, sum, off);
    float inv = 1.f / sum;
    ft[lane]     = v[0]*inv;
    ft[lane+32]  = v[1]*inv;
    ft[lane+64]  = v[2]*inv;
    ft[lane+96]  = v[3]*inv;
    fc[lane]     = v[4]*inv;
}

// ---------------- G time (HMMA v3: natural tiles + ldmatrix.trans) ---------
// G1 (warps 0-3): g1[s][r] = sum_t qh[s][t]*qvr[t][r]; A=QH natural, B=V via trans
// G2 (warps 4-7): E[r][s] = sum_t quo[t][r]*qh[t][s]; A=U via trans, B=QH via trans
__global__ __launch_bounds__(256, 2) void k_gt_mma() {
    extern __shared__ char smem[];
    const int tid = threadIdx.x;
    const u32 sbase = (u32)__cvta_generic_to_shared(smem);
    int nh = blockIdx.x;
    int n = nh >> 3, h = nh & 7;
    const float* qh = d_F_t + (long long)nh*16384;
    const float* vb = d_qvr_t + nh*4096;
    const float* ub = d_quo_t + nh*4096;
    const int lane = tid & 31, warp = tid >> 5;

    // build: qh natural split [128 s][136 t]
#pragma unroll
    for (int t = 0; t < 16; t++) {
        int li = tid + t * 256;
        int row = li >> 5, c4 = li & 31;
        float4 x = *reinterpret_cast<const float4*>(qh + row*128 + c4*4);
        float xs[4];
        xs[0] = x.x; xs[1] = x.y; xs[2] = x.z; xs[3] = x.w;
        __align__(8) __nv_bfloat16 b0[4], b1[4];
#pragma unroll
        for (int j = 0; j < 4; j++) {
            b0[j] = __float2bfloat16(xs[j]);
            b1[j] = __float2bfloat16(xs[j] - __bfloat162float(b0[j]));
        }
        int off = row*272 + c4*8;
        *reinterpret_cast<uint2*>(smem + GQH0 + off) = *reinterpret_cast<uint2*>(b0);
        *reinterpret_cast<uint2*>(smem + GQH1 + off) = *reinterpret_cast<uint2*>(b1);
    }
    // build: v,u natural split [128 t][40 r-pad]
    {
        int row = tid >> 1, half = tid & 1;
#pragma unroll
        for (int j = 0; j < 4; j++) {
            float4 x = *reinterpret_cast<const float4*>(vb + row*32 + half*16 + j*4);
            float xs[4];
            xs[0] = x.x; xs[1] = x.y; xs[2] = x.z; xs[3] = x.w;
            __align__(8) __nv_bfloat16 b0[4], b1[4];
#pragma unroll
            for (int e = 0; e < 4; e++) {
                b0[e] = __float2bfloat16(xs[e]);
                b1[e] = __float2bfloat16(xs[e] - __bfloat162float(b0[e]));
            }
            int off = row*80 + (half*16 + j*4)*2;
            *reinterpret_cast<uint2*>(smem + GV0 + off) = *reinterpret_cast<uint2*>(b0);
            *reinterpret_cast<uint2*>(smem + GV1 + off) = *reinterpret_cast<uint2*>(b1);
        }
#pragma unroll
        for (int j = 0; j < 4; j++) {
            float4 x = *reinterpret_cast<const float4*>(ub + row*32 + half*16 + j*4);
            float xs[4];
            xs[0] = x.x; xs[1] = x.y; xs[2] = x.z; xs[3] = x.w;
            __align__(8) __nv_bfloat16 b0[4], b1[4];
#pragma unroll
            for (int e = 0; e < 4; e++) {
                b0[e] = __float2bfloat16(xs[e]);
                b1[e] = __float2bfloat16(xs[e] - __bfloat162float(b0[e]));
            }
            int off = row*80 + (half*16 + j*4)*2;
            *reinterpret_cast<uint2*>(smem + GU0 + off) = *reinterpret_cast<uint2*>(b0);
            *reinterpret_cast<uint2*>(smem + GU1 + off) = *reinterpret_cast<uint2*>(b1);
        }
    }
    __syncthreads();

    float acc[2][4][4];
#pragma unroll
    for (int mt = 0; mt < 2; mt++)
#pragma unroll
        for (int nt = 0; nt < 4; nt++)
#pragma unroll
            for (int e = 0; e < 4; e++) acc[mt][nt][e] = 0.f;

    // trans address components (shared by V/U and QH trans loads)
    int trow = (lane & 7) + ((lane >> 4) << 3);     // row offset within 16-chunk
    int tcol8 = ((lane >> 3) & 1) * 8;              // col offset 0/8

    if (warp < 4) {
        u32 wbase = (u32)warp * 32;
#pragma unroll
        for (int k0 = 0; k0 < 8; k0++) {
            u32 a[2][2][4];
#pragma unroll
            for (int sp = 0; sp < 2; sp++)
#pragma unroll
                for (int mt = 0; mt < 2; mt++)
                    ldm_x4(a[sp][mt], sbase + (sp ? GQH1 : GQH0)
                           + (wbase + mt*16 + (lane & 15))*272 + k0*32 + (lane >> 4)*16);
            u32 b[2][4][2];
#pragma unroll
            for (int sp = 0; sp < 2; sp++)
#pragma unroll
                for (int rb = 0; rb < 2; rb++) {
                    u32 tr[4];
                    ldm_x4_t(tr, sbase + (sp ? GV1 : GV0)
                             + (k0*16 + trow)*80 + (rb*16 + tcol8)*2);
                    b[sp][2*rb][0] = tr[0];   b[sp][2*rb][1] = tr[2];
                    b[sp][2*rb+1][0] = tr[1]; b[sp][2*rb+1][1] = tr[3];
                }
#pragma unroll
            for (int mt = 0; mt < 2; mt++)
#pragma unroll
                for (int nt = 0; nt < 4; nt++) {
                    mma_bf16(acc[mt][nt], a[0][mt], b[0][nt]);
                    mma_bf16(acc[mt][nt], a[0][mt], b[1][nt]);
                    mma_bf16(acc[mt][nt], a[1][mt], b[0][nt]);
                }
        }
        // epilogue G1 (verified in R12)
#pragma unroll
        for (int mt = 0; mt < 2; mt++) {
            int s0 = (int)wbase + mt*16 + (lane >> 2);
#pragma unroll
            for (int nt = 0; nt < 2; nt++) {
                int rbase = nt*8 + (lane & 3)*2;
#pragma unroll
                for (int e = 0; e < 4; e++) {
                    int s = s0 + ((e >> 1) << 3);
                    int ci = rbase + (e & 1);
                    float c = d_cos[s*16 + ci], sn = d_sin[s*16 + ci];
                    float xl = acc[mt][nt][e], xh = acc[mt][nt+2][e];
                    long long rb2 = (long long)(n*128 + s) * 512;
                    int col = h*32 + ci;
                    st_split(d_ga0_t, d_ga1_t, rb2 + col,      xl*c + xh*sn);
                    st_split(d_ga0_t, d_ga1_t, rb2 + col + 16, xh*c - xl*sn);
                }
            }
        }
    } else {
        u32 sb_s = (u32)(warp - 4) * 32;
#pragma unroll
        for (int k0 = 0; k0 < 8; k0++) {
            u32 a[2][2][4];
#pragma unroll
            for (int sp = 0; sp < 2; sp++)
#pragma unroll
                for (int mt = 0; mt < 2; mt++)
                    ldm_x4_t(a[sp][mt], sbase + (sp ? GU1 : GU0)
                             + (k0*16 + trow)*80 + (mt*16 + tcol8)*2);
            u32 b[2][4][2];
#pragma unroll
            for (int sp = 0; sp < 2; sp++)
#pragma unroll
                for (int sb8 = 0; sb8 < 2; sb8++) {
                    u32 tr[4];
                    ldm_x4_t(tr, sbase + (sp ? GQH1 : GQH0)
                             + (k0*16 + trow)*272 + (sb_s + sb8*16 + tcol8)*2);
                    b[sp][2*sb8][0] = tr[0];   b[sp][2*sb8][1] = tr[2];
                    b[sp][2*sb8+1][0] = tr[1]; b[sp][2*sb8+1][1] = tr[3];
                }
#pragma unroll
            for (int mt = 0; mt < 2; mt++)
#pragma unroll
                for (int nt = 0; nt < 4; nt++) {
                    mma_bf16(acc[mt][nt], a[0][mt], b[0][nt]);
                    mma_bf16(acc[mt][nt], a[0][mt], b[1][nt]);
                    mma_bf16(acc[mt][nt], a[1][mt], b[0][nt]);
                }
        }
        // epilogue G2 (verified in R12)
#pragma unroll
        for (int nt = 0; nt < 4; nt++) {
            int sb = (int)sb_s + nt*8 + (lane & 3)*2;
#pragma unroll
            for (int e = 0; e < 4; e++) {
                int s = sb + (e & 1);
                int r = (lane >> 2) + ((e >> 1) << 3);
                float c = d_cos[s*16 + r], sn = d_sin[s*16 + r];
                float yl = acc[0][nt][e], yh = acc[1][nt][e];
                long long rb2 = (long long)(n*128 + s) * 512;
                int col = 256 + h*32 + r;
                st_split(d_ga0_t, d_ga1_t, rb2 + col,      yl*c - yh*sn);
                st_split(d_ga0_t, d_ga1_t, rb2 + col + 16, yh*c + yl*sn);
            }
        }
    }
}

// ---------------- G chan (FFMA, small) --------------------------------------
__global__ __launch_bounds__(128) void k_gc() {
    __shared__ float Qn[32][34];
    __shared__ float Vs[32][34];
    __shared__ float Us[32][34];
    int nh = blockIdx.x;
    int n = nh >> 3, h = nh & 7;
    const float* qh = d_F_c + (long long)nh*1024;
    const float* vb = d_qvr_c + nh*1024;
    const float* ub = d_quo_c + nh*1024;
    int tid = threadIdx.x;
#pragma unroll
    for (int l = 0; l < 2; l++) {
        int lin = tid + l*128;
        int t = lin >> 3, sq = (lin & 7) << 2;
        float4 q = *(const float4*)(qh + t*32 + sq);
        Qn[t][sq] = q.x; Qn[t][sq+1] = q.y; Qn[t][sq+2] = q.z; Qn[t][sq+3] = q.w;
        float4 v = *(const float4*)(vb + t*32 + sq);
        Vs[t][sq] = v.x; Vs[t][sq+1] = v.y; Vs[t][sq+2] = v.z; Vs[t][sq+3] = v.w;
        float4 u = *(const float4*)(ub + t*32 + sq);
        Us[t][sq] = u.x; Us[t][sq+1] = u.y; Us[t][sq+2] = u.z; Us[t][sq+3] = u.w;
    }
    __syncthreads();
    int rg = tid & 7, sg = tid >> 3;
    float a1[2][4], a2[2][4];
#pragma unroll
    for (int i = 0; i < 2; i++)
#pragma unroll
        for (int j = 0; j < 4; j++) { a1[i][j] = 0.f; a2[i][j] = 0.f; }
#pragma unroll
    for (int t = 0; t < 32; t++) {
        float av[2], bv[2], vv[4], uv[4];
        av[0] = Qn[sg*2][t];
        av[1] = Qn[sg*2+1][t];
        float2 qb = *(const float2*)&Qn[t][sg*2];
        float2 v0 = *(const float2*)&Vs[t][rg*2];
        float2 v1 = *(const float2*)&Vs[t][rg*2+16];
        float2 u0 = *(const float2*)&Us[t][rg*2];
        float2 u1 = *(const float2*)&Us[t][rg*2+16];
        bv[0] = qb.x; bv[1] = qb.y;
        vv[0] = v0.x; vv[1] = v0.y; vv[2] = v1.x; vv[3] = v1.y;
        uv[0] = u0.x; uv[1] = u0.y; uv[2] = u1.x; uv[3] = u1.y;
#pragma unroll
        for (int si = 0; si < 2; si++)
#pragma unroll
            for (int rj = 0; rj < 4; rj++) {
                a1[si][rj] += av[si]*vv[rj];
                a2[si][rj] += bv[si]*uv[rj];
            }
    }
#pragma unroll
    for (int si = 0; si < 2; si++) {
        int s = sg*2 + si;
        long long rb = (long long)(n*32 + s) * 512;
#pragma unroll
        for (int rj = 0; rj < 2; rj++) {
            int r = rg*2 + rj;
            float c  = d_cos[s*16 + r];
            float sn = d_sin[s*16 + r];
            float xl = a1[si][rj], xh = a1[si][rj+2];
            float yl = a2[si][rj], yh = a2[si][rj+2];
            int col = h*32 + r;
            st_split(d_ga0_c, d_ga1_c, rb + col,        xl*c + xh*sn);
            st_split(d_ga0_c, d_ga1_c, rb + col + 16,   xh*c - xl*sn);
            st_split(d_ga0_c, d_ga1_c, rb + 256 + col,      yl*c - yh*sn);
            st_split(d_ga0_c, d_ga1_c, rb + 256 + col + 16, yh*c + yl*sn);
        }
    }
}

// ---------------- launch ---------------------------------------------------
extern "C" void kernel_launch(void* const* d_in, const int* in_sizes, int n_in,
                              void* d_out, int out_size)
{
    const float* qz = (const float*)d_in[0];
    const float* mask_t = (const float*)d_in[1];
    const float* mask_c = (const float*)d_in[2];
    const float* u_t = (const float*)d_in[3];
    const float* v_t = (const float*)d_in[4];
    const float* u_c = (const float*)d_in[5];
    const float* v_c = (const float*)d_in[6];
    float* out = (float*)d_out;

    cudaFuncSetAttribute(k_proj_mma, cudaFuncAttributeMaxDynamicSharedMemorySize, PROJ_SMEM);
    cudaFuncSetAttribute(k_final_mma, cudaFuncAttributeMaxDynamicSharedMemorySize, FIN_SMEM);
    cudaFuncSetAttribute(k_gt_mma, cudaFuncAttributeMaxDynamicSharedMemorySize, GT_SMEM);

    k_setup<<<8, 256>>>();
    k_split_qz<<<8192, 256>>>(qz);
    k_split_w<<<512, 256>>>(u_t, v_t, 0);
    k_proj_mma<<<dim3(4, 256), 256, PROJ_SMEM>>>(0);   // my idx 3 -> ncu target
    k_split_w<<<512, 256>>>(u_c, v_c, 1);
    k_proj_mma<<<dim3(4, 256), 256, PROJ_SMEM>>>(1);

    k_split_wf<<<512, 256>>>(u_t, v_t, 0);
    k_ft<<<NT*HH, 256>>>(mask_t);
    k_fc<<<NC*HH, 256>>>(mask_c);

    k_softmax<<<32768, 256>>>();

    k_gt_mma<<<NT*HH, 256, GT_SMEM>>>();
    k_gc<<<NC*HH, 128>>>();

    k_split_wf<<<512, 256>>>(u_c, v_c, 1);
    k_final_mma<<<dim3(2, 256), 256, FIN_SMEM>>>(out, 0);
    k_final_mma<<<dim3(2, 256), 256, FIN_SMEM>>>(out + OUT_HALF, 1);
}

// round 15
// speedup vs baseline: 1.1770x; 1.0419x over previous
#include <cuda_runtime.h>
#include <cuda_bf16.h>

typedef unsigned int u32;
typedef unsigned long long u64;

// Problem constants
#define BB 8
#define CC 32
#define PP 128
#define DD 256
#define HH 8
#define RR 32
#define NT (BB*CC)
#define NC (BB*PP)
#define ROWS 32768
#define OUT_HALF (BB*CC*PP*DD)

// ---------------- scratch ----------------
__device__ __align__(256) float d_qur_t[NT*HH*PP*RR];
__device__ __align__(256) float d_quo_t[NT*HH*PP*RR];
__device__ __align__(256) float d_qvr_t[NT*HH*PP*RR];
__device__ __align__(256) float d_qur_c[NC*HH*CC*RR];
__device__ __align__(256) float d_quo_c[NC*HH*CC*RR];
__device__ __align__(256) float d_qvr_c[NC*HH*CC*RR];
__device__ __align__(256) float d_F_t[NT*HH*PP*PP];
__device__ __align__(256) float d_F_c[NC*HH*CC*CC];
__device__ __align__(256) float d_cos[PP*16];
__device__ __align__(256) float d_sin[PP*16];

__device__ __align__(256) __nv_bfloat16 d_qz0[ROWS*256];
__device__ __align__(256) __nv_bfloat16 d_qz1[ROWS*256];
__device__ __align__(256) __nv_bfloat16 d_qz2[ROWS*256];
__device__ __align__(256) __nv_bfloat16 d_wp_t[3][512*256];
__device__ __align__(256) __nv_bfloat16 d_wp_c[3][512*256];
__device__ __align__(256) __nv_bfloat16 d_wf_t[2][256*512];
__device__ __align__(256) __nv_bfloat16 d_wf_c[2][256*512];
__device__ __align__(256) __nv_bfloat16 d_ga0_t[ROWS*512];
__device__ __align__(256) __nv_bfloat16 d_ga1_t[ROWS*512];
__device__ __align__(256) __nv_bfloat16 d_ga0_c[ROWS*512];
__device__ __align__(256) __nv_bfloat16 d_ga1_c[ROWS*512];

// ---------------- HMMA + cp.async helpers (baseline PTX) -------------------
__device__ __forceinline__ void ldm_x4(u32* r, u32 addr) {
    asm volatile("ldmatrix.sync.aligned.m8n8.x4.shared.b16 {%0, %1, %2, %3}, [%4];" : "=r"(r[0]), "=r"(r[1]), "=r"(r[2]), "=r"(r[3]) : "r"(addr));
}
__device__ __forceinline__ void ldm_x4_t(u32* r, u32 addr) {
    asm volatile("ldmatrix.sync.aligned.m8n8.x4.trans.shared.b16 {%0, %1, %2, %3}, [%4];" : "=r"(r[0]), "=r"(r[1]), "=r"(r[2]), "=r"(r[3]) : "r"(addr));
}
__device__ __forceinline__ void mma_bf16(float* d, const u32* a, const u32* b) {
    asm volatile("mma.sync.aligned.m16n8k16.row.col.f32.bf16.bf16.f32 {%0, %1, %2, %3}, {%4, %5, %6, %7}, {%8, %9}, {%0, %1, %2, %3};" : "+f"(d[0]), "+f"(d[1]), "+f"(d[2]), "+f"(d[3]) : "r"(a[0]), "r"(a[1]), "r"(a[2]), "r"(a[3]), "r"(b[0]), "r"(b[1]));
}
__device__ __forceinline__ void cpa(u32 s, const __nv_bfloat16* g) {
    asm volatile("cp.async.ca.shared.global [%0], [%1], 16;" :: "r"(s), "l"((u64)__cvta_generic_to_global((void*)g)) : "memory");
}
__device__ __forceinline__ void cpa_commit() { asm volatile("cp.async.commit_group;" ::: "memory"); }
__device__ __forceinline__ void cpa_wait0() { asm volatile("cp.async.wait_group 0;" ::: "memory"); }
__device__ __forceinline__ void cpa_wait1() { asm volatile("cp.async.wait_group 1;" ::: "memory"); }

// 64B-stride tiles with chunk swizzle: conflict-free stores + ldmatrix reads
#define TILE_BYTES 8192         // 128 rows * 64 bytes
#define SWZ(row, seg) (((seg) ^ (((row) >> 1) & 3)))
#define PROJ_SMEM (2*6*TILE_BYTES)   // 96 KB -> 2 CTAs/SM
#define FIN_SMEM  (2*4*TILE_BYTES)   // 64 KB -> 2 CTAs/SM

// k_gt_mma smem (unchanged, natural layouts; stride 272B QH / 80B V,U)
#define GQH0 0
#define GQH1 34816
#define GV0  69632
#define GV1  79872
#define GU0  90112
#define GU1  100352
#define GT_SMEM 110592

__device__ __forceinline__ void st_split(__nv_bfloat16* A0, __nv_bfloat16* A1,
                                         long long i, float x) {
    __nv_bfloat16 b0 = __float2bfloat16(x);
    A0[i] = b0;
    A1[i] = __float2bfloat16(x - __bfloat162float(b0));
}

// ---------------- rope table ----------------
__global__ void k_setup() {
    int idx = blockIdx.x * blockDim.x + threadIdx.x;
    if (idx < PP*16) {
        int s = idx >> 4, i = idx & 15;
        double invf = pow(10000.0, -((double)(2*i)) / 32.0);
        double a = (double)s * invf;
        d_cos[idx] = (float)cos(a);
        d_sin[idx] = (float)sin(a);
    }
}

// ---------------- split qz into 3 bf16 components --------------------------
__global__ __launch_bounds__(256) void k_split_qz(const float* __restrict__ qz) {
    int i = (blockIdx.x * 256 + threadIdx.x) * 4;
    float4 x = *reinterpret_cast<const float4*>(qz + i);
    float xs[4];
    xs[0] = x.x; xs[1] = x.y; xs[2] = x.z; xs[3] = x.w;
    __align__(8) __nv_bfloat16 b0[4], b1[4], b2[4];
#pragma unroll
    for (int j = 0; j < 4; j++) {
        b0[j] = __float2bfloat16(xs[j]);
        float r = xs[j] - __bfloat162float(b0[j]);
        b1[j] = __float2bfloat16(r);
        b2[j] = __float2bfloat16(r - __bfloat162float(b1[j]));
    }
    *reinterpret_cast<uint2*>(&d_qz0[i]) = *reinterpret_cast<uint2*>(b0);
    *reinterpret_cast<uint2*>(&d_qz1[i]) = *reinterpret_cast<uint2*>(b1);
    *reinterpret_cast<uint2*>(&d_qz2[i]) = *reinterpret_cast<uint2*>(b2);
}

__global__ __launch_bounds__(256) void k_split_w(const float* __restrict__ U,
                                                 const float* __restrict__ V, int branch) {
    int idx = blockIdx.x * 256 + threadIdx.x;
    int n = idx >> 8, k = idx & 255;
    float x = (n < 256) ? U[n*256 + k] : V[(n-256)*256 + k];
    __nv_bfloat16* w0 = branch ? d_wp_c[0] : d_wp_t[0];
    __nv_bfloat16* w1 = branch ? d_wp_c[1] : d_wp_t[1];
    __nv_bfloat16* w2 = branch ? d_wp_c[2] : d_wp_t[2];
    __nv_bfloat16 b0 = __float2bfloat16(x);
    float r = x - __bfloat162float(b0);
    __nv_bfloat16 b1 = __float2bfloat16(r);
    w0[idx] = b0; w1[idx] = b1;
    w2[idx] = __float2bfloat16(r - __bfloat162float(b1));
}

__global__ __launch_bounds__(256) void k_split_wf(const float* __restrict__ U,
                                                  const float* __restrict__ V, int branch) {
    int idx = blockIdx.x * 256 + threadIdx.x;
    int n = idx >> 9, k = idx & 511;
    float x = (k < 256) ? U[k*256 + n] : V[(k-256)*256 + n];
    __nv_bfloat16* w0 = branch ? d_wf_c[0] : d_wf_t[0];
    __nv_bfloat16* w1 = branch ? d_wf_c[1] : d_wf_t[1];
    __nv_bfloat16 b0 = __float2bfloat16(x);
    w0[idx] = b0;
    w1[idx] = __float2bfloat16(x - __bfloat162float(b0));
}

// ---------------- proj GEMM (HMMA, cp.async, swizzled smem, fused RoPE) ----
__global__ __launch_bounds__(256, 2) void k_proj_mma(int branch) {
    extern __shared__ char smem[];
    const int tid = threadIdx.x;
    const u32 sbase = (u32)__cvta_generic_to_shared(smem);
    const int n0 = blockIdx.x * 128;
    const int m0 = blockIdx.y * 128;
    const int lane = tid & 31, warp = tid >> 5;
    const int wm = warp >> 1, wn = warp & 1;
    const __nv_bfloat16* W0 = branch ? d_wp_c[0] : d_wp_t[0];
    const __nv_bfloat16* W1 = branch ? d_wp_c[1] : d_wp_t[1];
    const __nv_bfloat16* W2 = branch ? d_wp_c[2] : d_wp_t[2];

    float acc[2][8][4];
#pragma unroll
    for (int mt = 0; mt < 2; mt++)
#pragma unroll
        for (int nt = 0; nt < 8; nt++)
#pragma unroll
            for (int e = 0; e < 4; e++) acc[mt][nt][e] = 0.f;

#pragma unroll 1
    for (int kc = -1; kc < 8; kc++) {
        int ld = kc + 1;
        if (ld < 8) {
            u32 stb = sbase + (u32)(ld & 1) * (6*TILE_BYTES);
#pragma unroll
            for (int t = 0; t < 12; t++) {
                int li = tid + t * 256;
                int seg = li & 3, row = (li >> 2) & 127, tile = li >> 9;
                const __nv_bfloat16* src;
                if (tile < 3) {
                    int grow = m0 + row;
                    if (branch) {
                        int b = grow >> 12, rem = grow & 4095;
                        grow = ((b << 5) + (rem & 31)) * 128 + (rem >> 5);
                    }
                    const __nv_bfloat16* A = (tile == 0) ? d_qz0 : (tile == 1) ? d_qz1 : d_qz2;
                    src = A + (long long)grow * 256 + ld * 32 + seg * 8;
                } else {
                    const __nv_bfloat16* W = (tile == 3) ? W0 : (tile == 4) ? W1 : W2;
                    src = W + (long long)(n0 + row) * 256 + ld * 32 + seg * 8;
                }
                cpa(stb + (u32)(tile * TILE_BYTES + row * 64 + SWZ(row, seg) * 16), src);
            }
            cpa_commit();
        }
        if (kc < 0) continue;
        if (kc < 7) cpa_wait1(); else cpa_wait0();
        __syncthreads();
        u32 stb = sbase + (u32)(kc & 1) * (6*TILE_BYTES);
#pragma unroll
        for (int ks = 0; ks < 2; ks++) {
            int seg = ks * 2 + (lane >> 4);
            u32 afr[3][2][4];
#pragma unroll
            for (int sp = 0; sp < 3; sp++)
#pragma unroll
                for (int mt = 0; mt < 2; mt++) {
                    int row = wm * 32 + mt * 16 + (lane & 15);
                    ldm_x4(afr[sp][mt], stb + sp * TILE_BYTES + row * 64 + SWZ(row, seg) * 16);
                }
#pragma unroll
            for (int sb = 0; sb < 3; sb++) {
                u32 bfr[8][2];
#pragma unroll
                for (int g = 0; g < 4; g++) {
                    u32 tr[4];
                    int row = wn * 64 + g * 16 + (lane & 15);
                    ldm_x4(tr, stb + (3 + sb) * TILE_BYTES + row * 64 + SWZ(row, seg) * 16);
                    bfr[2*g][0] = tr[0];   bfr[2*g][1] = tr[2];
                    bfr[2*g+1][0] = tr[1]; bfr[2*g+1][1] = tr[3];
                }
                int na = 3 - sb;
#pragma unroll
                for (int sa = 0; sa < 3; sa++) {
                    if (sa < na) {
#pragma unroll
                        for (int mt = 0; mt < 2; mt++)
#pragma unroll
                            for (int nt = 0; nt < 8; nt++)
                                mma_bf16(acc[mt][nt], afr[sa][mt], bfr[nt]);
                    }
                }
            }
        }
        __syncthreads();
    }

    // fused RoPE epilogue
    float* OUR = branch ? d_qur_c : d_qur_t;
    float* OUO = branch ? d_quo_c : d_quo_t;
    float* OVR = branch ? d_qvr_c : d_qvr_t;
    const int Sbits = branch ? 5 : 7;
    const int Smask = (1 << Sbits) - 1;
    const int isQV = (n0 >= 256);
#pragma unroll
    for (int mt = 0; mt < 2; mt++) {
        int rA = m0 + wm * 32 + mt * 16 + (lane >> 2);
        int rB = rA + 8;
        int nA = rA >> Sbits, sA = rA & Smask;
        int nB = rB >> Sbits, sB = rB & Smask;
#pragma unroll
        for (int nt = 0; nt < 8; nt++) {
            int colh = (n0 & 255) + wn * 64 + nt * 8;
            int rr = (colh & 31) + (lane & 3) * 2;
            int h = (colh >> 5) & 7;
            float sgn = (rr < 16) ? -1.f : 1.f;
            int ci = rr & 15;
            float cA0 = d_cos[sA*16 + ci],     snA0 = d_sin[sA*16 + ci];
            float cA1 = d_cos[sA*16 + ci + 1], snA1 = d_sin[sA*16 + ci + 1];
            float cB0 = d_cos[sB*16 + ci],     snB0 = d_sin[sB*16 + ci];
            float cB1 = d_cos[sB*16 + ci + 1], snB1 = d_sin[sB*16 + ci + 1];
            float q0 = acc[mt][nt][0], q1 = acc[mt][nt][1];
            float q2 = acc[mt][nt][2], q3 = acc[mt][nt][3];
            float p0 = acc[mt][nt ^ 2][0], p1 = acc[mt][nt ^ 2][1];
            float p2 = acc[mt][nt ^ 2][2], p3 = acc[mt][nt ^ 2][3];
            long long baseA = (((long long)(nA * 8 + h) << Sbits) + sA) * 32 + rr;
            long long baseB = (((long long)(nB * 8 + h) << Sbits) + sB) * 32 + rr;
            if (!isQV) {
                float2 w;
                w.x = q0*cA0 + sgn*p0*snA0; w.y = q1*cA1 + sgn*p1*snA1;
                *reinterpret_cast<float2*>(&OUR[baseA]) = w;
                w.x = q0*cA0 - sgn*p0*snA0; w.y = q1*cA1 - sgn*p1*snA1;
                *reinterpret_cast<float2*>(&OUO[baseA]) = w;
                w.x = q2*cB0 + sgn*p2*snB0; w.y = q3*cB1 + sgn*p3*snB1;
                *reinterpret_cast<float2*>(&OUR[baseB]) = w;
                w.x = q2*cB0 - sgn*p2*snB0; w.y = q3*cB1 - sgn*p3*snB1;
                *reinterpret_cast<float2*>(&OUO[baseB]) = w;
            } else {
                float2 w;
                w.x = q0*cA0 + sgn*p0*snA0; w.y = q1*cA1 + sgn*p1*snA1;
                *reinterpret_cast<float2*>(&OVR[baseA]) = w;
                w.x = q2*cB0 + sgn*p2*snB0; w.y = q3*cB1 + sgn*p3*snB1;
                *reinterpret_cast<float2*>(&OVR[baseB]) = w;
            }
        }
    }
}

// ---------------- final GEMM (HMMA, cp.async, swizzled smem) ---------------
__global__ __launch_bounds__(256, 2) void k_final_mma(float* __restrict__ out, int branch) {
    extern __shared__ char smem[];
    const int tid = threadIdx.x;
    const u32 sbase = (u32)__cvta_generic_to_shared(smem);
    const int n0 = blockIdx.x * 128;
    const int m0 = blockIdx.y * 128;
    const int lane = tid & 31, warp = tid >> 5;
    const int wm = warp >> 1, wn = warp & 1;
    const __nv_bfloat16* G0 = branch ? d_ga0_c : d_ga0_t;
    const __nv_bfloat16* G1 = branch ? d_ga1_c : d_ga1_t;
    const __nv_bfloat16* F0 = branch ? d_wf_c[0] : d_wf_t[0];
    const __nv_bfloat16* F1 = branch ? d_wf_c[1] : d_wf_t[1];

    float acc[2][8][4];
#pragma unroll
    for (int mt = 0; mt < 2; mt++)
#pragma unroll
        for (int nt = 0; nt < 8; nt++)
#pragma unroll
            for (int e = 0; e < 4; e++) acc[mt][nt][e] = 0.f;

#pragma unroll 1
    for (int kc = -1; kc < 16; kc++) {
        int ld = kc + 1;
        if (ld < 16) {
            u32 stb = sbase + (u32)(ld & 1) * (4*TILE_BYTES);
#pragma unroll
            for (int t = 0; t < 8; t++) {
                int li = tid + t * 256;
                int seg = li & 3, row = (li >> 2) & 127, tile = li >> 9;
                const __nv_bfloat16* src;
                if (tile == 0)      src = G0 + (long long)(m0 + row) * 512 + ld * 32 + seg * 8;
                else if (tile == 1) src = G1 + (long long)(m0 + row) * 512 + ld * 32 + seg * 8;
                else if (tile == 2) src = F0 + (long long)(n0 + row) * 512 + ld * 32 + seg * 8;
                else                src = F1 + (long long)(n0 + row) * 512 + ld * 32 + seg * 8;
                cpa(stb + (u32)(tile * TILE_BYTES + row * 64 + SWZ(row, seg) * 16), src);
            }
            cpa_commit();
        }
        if (kc < 0) continue;
        if (kc < 15) cpa_wait1(); else cpa_wait0();
        __syncthreads();
        u32 stb = sbase + (u32)(kc & 1) * (4*TILE_BYTES);
#pragma unroll
        for (int ks = 0; ks < 2; ks++) {
            int seg = ks * 2 + (lane >> 4);
            u32 afr[2][2][4];
#pragma unroll
            for (int sp = 0; sp < 2; sp++)
#pragma unroll
                for (int mt = 0; mt < 2; mt++) {
                    int row = wm * 32 + mt * 16 + (lane & 15);
                    ldm_x4(afr[sp][mt], stb + sp * TILE_BYTES + row * 64 + SWZ(row, seg) * 16);
                }
#pragma unroll
            for (int sb = 0; sb < 2; sb++) {
                u32 bfr[8][2];
#pragma unroll
                for (int g = 0; g < 4; g++) {
                    u32 tr[4];
                    int row = wn * 64 + g * 16 + (lane & 15);
                    ldm_x4(tr, stb + (2 + sb) * TILE_BYTES + row * 64 + SWZ(row, seg) * 16);
                    bfr[2*g][0] = tr[0];   bfr[2*g][1] = tr[2];
                    bfr[2*g+1][0] = tr[1]; bfr[2*g+1][1] = tr[3];
                }
                int na = 2 - sb;
#pragma unroll
                for (int sa = 0; sa < 2; sa++) {
                    if (sa < na) {
#pragma unroll
                        for (int mt = 0; mt < 2; mt++)
#pragma unroll
                            for (int nt = 0; nt < 8; nt++)
                                mma_bf16(acc[mt][nt], afr[sa][mt], bfr[nt]);
                    }
                }
            }
        }
        __syncthreads();
    }
#pragma unroll
    for (int mt = 0; mt < 2; mt++)
#pragma unroll
        for (int nt = 0; nt < 8; nt++) {
            int r = m0 + wm * 32 + mt * 16 + (lane >> 2);
            int c = n0 + wn * 64 + nt * 8 + (lane & 3) * 2;
            long long r0o, r1o;
            if (!branch) {
                r0o = (long long)r; r1o = (long long)(r + 8);
            } else {
                int nn = r >> 5, cc2 = r & 31;
                int b = nn >> 7, p = nn & 127;
                r0o = (long long)((b * 32 + cc2) * 128 + p);
                int r8 = r + 8;
                nn = r8 >> 5; cc2 = r8 & 31; b = nn >> 7; p = nn & 127;
                r1o = (long long)((b * 32 + cc2) * 128 + p);
            }
            float2 lo; lo.x = acc[mt][nt][0]; lo.y = acc[mt][nt][1];
            float2 hi; hi.x = acc[mt][nt][2]; hi.y = acc[mt][nt][3];
            *reinterpret_cast<float2*>(&out[r0o * 256 + c]) = lo;
            *reinterpret_cast<float2*>(&out[r1o * 256 + c]) = hi;
        }
}

// ---------------- F_t -------------------------------------------------------
__global__ __launch_bounds__(256) void k_ft(const float* __restrict__ mask) {
    __shared__ float SuT[32][132];
    __shared__ float SvT[32][132];
    int nh = blockIdx.x;
    int n = nh >> 3;
    const float* ubase = d_qur_t + nh*128*32;
    const float* vbase = d_qvr_t + nh*128*32;
    int tid = threadIdx.x;
#pragma unroll
    for (int l = 0; l < 4; l++) {
        int lin = tid + l*256;
        int s = lin >> 3, rq = (lin & 7) << 2;
        float4 u = *reinterpret_cast<const float4*>(ubase + s*32 + rq);
        SuT[rq][s] = u.x; SuT[rq+1][s] = u.y; SuT[rq+2][s] = u.z; SuT[rq+3][s] = u.w;
        float4 v = *reinterpret_cast<const float4*>(vbase + s*32 + rq);
        SvT[rq][s] = v.x; SvT[rq+1][s] = v.y; SvT[rq+2][s] = v.z; SvT[rq+3][s] = v.w;
    }
    __syncthreads();
    int tx = tid & 15, ty = tid >> 4;
    float acc[8][8];
#pragma unroll
    for (int i = 0; i < 8; i++)
#pragma unroll
        for (int j = 0; j < 8; j++) acc[i][j] = 0.f;
#pragma unroll
    for (int k = 0; k < 32; k++) {
        float a[8], b[8];
        *(float4*)&a[0] = *(const float4*)&SuT[k][ty*8];
        *(float4*)&a[4] = *(const float4*)&SuT[k][ty*8+4];
        *(float4*)&b[0] = *(const float4*)&SvT[k][tx*8];
        *(float4*)&b[4] = *(const float4*)&SvT[k][tx*8+4];
#pragma unroll
        for (int i = 0; i < 8; i++)
#pragma unroll
            for (int j = 0; j < 8; j++) acc[i][j] += a[i]*b[j];
    }
    float* fout = d_F_t + (long long)nh*16384;
    const float* mrow = mask + (long long)n*16384;
#pragma unroll
    for (int i = 0; i < 8; i++) {
        int s = ty*8 + i;
#pragma unroll
        for (int j4 = 0; j4 < 2; j4++) {
            int t = tx*8 + j4*4;
            float4 m4 = *reinterpret_cast<const float4*>(mrow + s*128 + t);
            float4 o;
            o.x = acc[i][j4*4]   + m4.x;
            o.y = acc[i][j4*4+1] + m4.y;
            o.z = acc[i][j4*4+2] + m4.z;
            o.w = acc[i][j4*4+3] + m4.w;
            *reinterpret_cast<float4*>(fout + s*128 + t) = o;
        }
    }
}

// ---------------- F_c -------------------------------------------------------
__global__ __launch_bounds__(256) void k_fc(const float* __restrict__ mask) {
    __shared__ float SuT[32][36];
    __shared__ float SvT[32][36];
    int nh = blockIdx.x;
    int n = nh >> 3;
    const float* ubase = d_qur_c + nh*1024;
    const float* vbase = d_qvr_c + nh*1024;
    int tid = threadIdx.x;
    {
        int s = tid >> 3, rq = (tid & 7) << 2;
        float4 u = *reinterpret_cast<const float4*>(ubase + s*32 + rq);
        SuT[rq][s] = u.x; SuT[rq+1][s] = u.y; SuT[rq+2][s] = u.z; SuT[rq+3][s] = u.w;
        float4 v = *reinterpret_cast<const float4*>(vbase + s*32 + rq);
        SvT[rq][s] = v.x; SvT[rq+1][s] = v.y; SvT[rq+2][s] = v.z; SvT[rq+3][s] = v.w;
    }
    __syncthreads();
    int tx = tid & 7, ty = tid >> 3;
    float acc[4];
    acc[0] = 0.f; acc[1] = 0.f; acc[2] = 0.f; acc[3] = 0.f;
#pragma unroll
    for (int k = 0; k < 32; k++) {
        float a = SuT[k][ty];
        float4 b = *(const float4*)&SvT[k][tx*4];
        acc[0] += a*b.x; acc[1] += a*b.y; acc[2] += a*b.z; acc[3] += a*b.w;
    }
    int t0 = tx*4;
    float4 m4 = *reinterpret_cast<const float4*>(mask + (long long)n*1024 + ty*32 + t0);
    float4 o;
    o.x = acc[0] + m4.x; o.y = acc[1] + m4.y; o.z = acc[2] + m4.z; o.w = acc[3] + m4.w;
    *reinterpret_cast<float4*>(d_F_c + (long long)nh*1024 + ty*32 + t0) = o;
}

// ---------------- joint softmax --------------------------------------------
__global__ __launch_bounds__(256) void k_softmax() {
    int warp = threadIdx.x >> 5, lane = threadIdx.x & 31;
    int rowid = blockIdx.x * 8 + warp;
    int p  = rowid & 127;
    int r1 = rowid >> 7;
    int c  = r1 & 31;
    int r2 = r1 >> 5;
    int h  = r2 & 7;
    int b  = r2 >> 3;
    float* ft = d_F_t + ((long long)(((b*32 + c)*8 + h)*128 + p))*128;
    float* fc = d_F_c + ((long long)(((b*128 + p)*8 + h)*32 + c))*32;
    float v[5];
    v[0] = ft[lane]; v[1] = ft[lane+32]; v[2] = ft[lane+64]; v[3] = ft[lane+96];
    v[4] = fc[lane];
    float m = v[0];
#pragma unroll
    for (int i = 1; i < 5; i++) m = fmaxf(m, v[i]);
#pragma unroll
    for (int off = 16; off >= 1; off >>= 1)
        m = fmaxf(m, __shfl_xor_sync(0xffffffffu, m, off));
    float sum = 0.f;
#pragma unroll
    for (int i = 0; i < 5; i++) { v[i] = expf(256.f*(v[i] - m)); sum += v[i]; }
#pragma unroll
    for (int off = 16; off >= 1; off >>= 1)
        sum += __shfl_xor_sync(0xffffffffu, sum, off);
    float inv = 1.f / sum;
    ft[lane]     = v[0]*inv;
    ft[lane+32]  = v[1]*inv;
    ft[lane+64]  = v[2]*inv;
    ft[lane+96]  = v[3]*inv;
    fc[lane]     = v[4]*inv;
}

// ---------------- G time (HMMA, natural tiles + ldmatrix.trans) ------------
__global__ __launch_bounds__(256, 2) void k_gt_mma() {
    extern __shared__ char smem[];
    const int tid = threadIdx.x;
    const u32 sbase = (u32)__cvta_generic_to_shared(smem);
    int nh = blockIdx.x;
    int n = nh >> 3, h = nh & 7;
    const float* qh = d_F_t + (long long)nh*16384;
    const float* vb = d_qvr_t + nh*4096;
    const float* ub = d_quo_t + nh*4096;
    const int lane = tid & 31, warp = tid >> 5;

#pragma unroll
    for (int t = 0; t < 16; t++) {
        int li = tid + t * 256;
        int row = li >> 5, c4 = li & 31;
        float4 x = *reinterpret_cast<const float4*>(qh + row*128 + c4*4);
        float xs[4];
        xs[0] = x.x; xs[1] = x.y; xs[2] = x.z; xs[3] = x.w;
        __align__(8) __nv_bfloat16 b0[4], b1[4];
#pragma unroll
        for (int j = 0; j < 4; j++) {
            b0[j] = __float2bfloat16(xs[j]);
            b1[j] = __float2bfloat16(xs[j] - __bfloat162float(b0[j]));
        }
        int off = row*272 + c4*8;
        *reinterpret_cast<uint2*>(smem + GQH0 + off) = *reinterpret_cast<uint2*>(b0);
        *reinterpret_cast<uint2*>(smem + GQH1 + off) = *reinterpret_cast<uint2*>(b1);
    }
    {
        int row = tid >> 1, half = tid & 1;
#pragma unroll
        for (int j = 0; j < 4; j++) {
            float4 x = *reinterpret_cast<const float4*>(vb + row*32 + half*16 + j*4);
            float xs[4];
            xs[0] = x.x; xs[1] = x.y; xs[2] = x.z; xs[3] = x.w;
            __align__(8) __nv_bfloat16 b0[4], b1[4];
#pragma unroll
            for (int e = 0; e < 4; e++) {
                b0[e] = __float2bfloat16(xs[e]);
                b1[e] = __float2bfloat16(xs[e] - __bfloat162float(b0[e]));
            }
            int off = row*80 + (half*16 + j*4)*2;
            *reinterpret_cast<uint2*>(smem + GV0 + off) = *reinterpret_cast<uint2*>(b0);
            *reinterpret_cast<uint2*>(smem + GV1 + off) = *reinterpret_cast<uint2*>(b1);
        }
#pragma unroll
        for (int j = 0; j < 4; j++) {
            float4 x = *reinterpret_cast<const float4*>(ub + row*32 + half*16 + j*4);
            float xs[4];
            xs[0] = x.x; xs[1] = x.y; xs[2] = x.z; xs[3] = x.w;
            __align__(8) __nv_bfloat16 b0[4], b1[4];
#pragma unroll
            for (int e = 0; e < 4; e++) {
                b0[e] = __float2bfloat16(xs[e]);
                b1[e] = __float2bfloat16(xs[e] - __bfloat162float(b0[e]));
            }
            int off = row*80 + (half*16 + j*4)*2;
            *reinterpret_cast<uint2*>(smem + GU0 + off) = *reinterpret_cast<uint2*>(b0);
            *reinterpret_cast<uint2*>(smem + GU1 + off) = *reinterpret_cast<uint2*>(b1);
        }
    }
    __syncthreads();

    float acc[2][4][4];
#pragma unroll
    for (int mt = 0; mt < 2; mt++)
#pragma unroll
        for (int nt = 0; nt < 4; nt++)
#pragma unroll
            for (int e = 0; e < 4; e++) acc[mt][nt][e] = 0.f;

    int trow = (lane & 7) + ((lane >> 4) << 3);
    int tcol8 = ((lane >> 3) & 1) * 8;

    if (warp < 4) {
        u32 wbase = (u32)warp * 32;
#pragma unroll
        for (int k0 = 0; k0 < 8; k0++) {
            u32 a[2][2][4];
#pragma unroll
            for (int sp = 0; sp < 2; sp++)
#pragma unroll
                for (int mt = 0; mt < 2; mt++)
                    ldm_x4(a[sp][mt], sbase + (sp ? GQH1 : GQH0)
                           + (wbase + mt*16 + (lane & 15))*272 + k0*32 + (lane >> 4)*16);
            u32 b[2][4][2];
#pragma unroll
            for (int sp = 0; sp < 2; sp++)
#pragma unroll
                for (int rb = 0; rb < 2; rb++) {
                    u32 tr[4];
                    ldm_x4_t(tr, sbase + (sp ? GV1 : GV0)
                             + (k0*16 + trow)*80 + (rb*16 + tcol8)*2);
                    b[sp][2*rb][0] = tr[0];   b[sp][2*rb][1] = tr[2];
                    b[sp][2*rb+1][0] = tr[1]; b[sp][2*rb+1][1] = tr[3];
                }
#pragma unroll
            for (int mt = 0; mt < 2; mt++)
#pragma unroll
                for (int nt = 0; nt < 4; nt++) {
                    mma_bf16(acc[mt][nt], a[0][mt], b[0][nt]);
                    mma_bf16(acc[mt][nt], a[0][mt], b[1][nt]);
                    mma_bf16(acc[mt][nt], a[1][mt], b[0][nt]);
                }
        }
#pragma unroll
        for (int mt = 0; mt < 2; mt++) {
            int s0 = (int)wbase + mt*16 + (lane >> 2);
#pragma unroll
            for (int nt = 0; nt < 2; nt++) {
                int rbase = nt*8 + (lane & 3)*2;
#pragma unroll
                for (int e = 0; e < 4; e++) {
                    int s = s0 + ((e >> 1) << 3);
                    int ci = rbase + (e & 1);
                    float c = d_cos[s*16 + ci], sn = d_sin[s*16 + ci];
                    float xl = acc[mt][nt][e], xh = acc[mt][nt+2][e];
                    long long rb2 = (long long)(n*128 + s) * 512;
                    int col = h*32 + ci;
                    st_split(d_ga0_t, d_ga1_t, rb2 + col,      xl*c + xh*sn);
                    st_split(d_ga0_t, d_ga1_t, rb2 + col + 16, xh*c - xl*sn);
                }
            }
        }
    } else {
        u32 sb_s = (u32)(warp - 4) * 32;
#pragma unroll
        for (int k0 = 0; k0 < 8; k0++) {
            u32 a[2][2][4];
#pragma unroll
            for (int sp = 0; sp < 2; sp++)
#pragma unroll
                for (int mt = 0; mt < 2; mt++)
                    ldm_x4_t(a[sp][mt], sbase + (sp ? GU1 : GU0)
                             + (k0*16 + trow)*80 + (mt*16 + tcol8)*2);
            u32 b[2][4][2];
#pragma unroll
            for (int sp = 0; sp < 2; sp++)
#pragma unroll
                for (int sb8 = 0; sb8 < 2; sb8++) {
                    u32 tr[4];
                    ldm_x4_t(tr, sbase + (sp ? GQH1 : GQH0)
                             + (k0*16 + trow)*272 + (sb_s + sb8*16 + tcol8)*2);
                    b[sp][2*sb8][0] = tr[0];   b[sp][2*sb8][1] = tr[2];
                    b[sp][2*sb8+1][0] = tr[1]; b[sp][2*sb8+1][1] = tr[3];
                }
#pragma unroll
            for (int mt = 0; mt < 2; mt++)
#pragma unroll
                for (int nt = 0; nt < 4; nt++) {
                    mma_bf16(acc[mt][nt], a[0][mt], b[0][nt]);
                    mma_bf16(acc[mt][nt], a[0][mt], b[1][nt]);
                    mma_bf16(acc[mt][nt], a[1][mt], b[0][nt]);
                }
        }
#pragma unroll
        for (int nt = 0; nt < 4; nt++) {
            int sb = (int)sb_s + nt*8 + (lane & 3)*2;
#pragma unroll
            for (int e = 0; e < 4; e++) {
                int s = sb + (e & 1);
                int r = (lane >> 2) + ((e >> 1) << 3);
                float c = d_cos[s*16 + r], sn = d_sin[s*16 + r];
                float yl = acc[0][nt][e], yh = acc[1][nt][e];
                long long rb2 = (long long)(n*128 + s) * 512;
                int col = 256 + h*32 + r;
                st_split(d_ga0_t, d_ga1_t, rb2 + col,      yl*c - yh*sn);
                st_split(d_ga0_t, d_ga1_t, rb2 + col + 16, yh*c + yl*sn);
            }
        }
    }
}

// ---------------- G chan (FFMA, small) --------------------------------------
__global__ __launch_bounds__(128) void k_gc() {
    __shared__ float Qn[32][34];
    __shared__ float Vs[32][34];
    __shared__ float Us[32][34];
    int nh = blockIdx.x;
    int n = nh >> 3, h = nh & 7;
    const float* qh = d_F_c + (long long)nh*1024;
    const float* vb = d_qvr_c + nh*1024;
    const float* ub = d_quo_c + nh*1024;
    int tid = threadIdx.x;
#pragma unroll
    for (int l = 0; l < 2; l++) {
        int lin = tid + l*128;
        int t = lin >> 3, sq = (lin & 7) << 2;
        float4 q = *(const float4*)(qh + t*32 + sq);
        Qn[t][sq] = q.x; Qn[t][sq+1] = q.y; Qn[t][sq+2] = q.z; Qn[t][sq+3] = q.w;
        float4 v = *(const float4*)(vb + t*32 + sq);
        Vs[t][sq] = v.x; Vs[t][sq+1] = v.y; Vs[t][sq+2] = v.z; Vs[t][sq+3] = v.w;
        float4 u = *(const float4*)(ub + t*32 + sq);
        Us[t][sq] = u.x; Us[t][sq+1] = u.y; Us[t][sq+2] = u.z; Us[t][sq+3] = u.w;
    }
    __syncthreads();
    int rg = tid & 7, sg = tid >> 3;
    float a1[2][4], a2[2][4];
#pragma unroll
    for (int i = 0; i < 2; i++)
#pragma unroll
        for (int j = 0; j < 4; j++) { a1[i][j] = 0.f; a2[i][j] = 0.f; }
#pragma unroll
    for (int t = 0; t < 32; t++) {
        float av[2], bv[2], vv[4], uv[4];
        av[0] = Qn[sg*2][t];
        av[1] = Qn[sg*2+1][t];
        float2 qb = *(const float2*)&Qn[t][sg*2];
        float2 v0 = *(const float2*)&Vs[t][rg*2];
        float2 v1 = *(const float2*)&Vs[t][rg*2+16];
        float2 u0 = *(const float2*)&Us[t][rg*2];
        float2 u1 = *(const float2*)&Us[t][rg*2+16];
        bv[0] = qb.x; bv[1] = qb.y;
        vv[0] = v0.x; vv[1] = v0.y; vv[2] = v1.x; vv[3] = v1.y;
        uv[0] = u0.x; uv[1] = u0.y; uv[2] = u1.x; uv[3] = u1.y;
#pragma unroll
        for (int si = 0; si < 2; si++)
#pragma unroll
            for (int rj = 0; rj < 4; rj++) {
                a1[si][rj] += av[si]*vv[rj];
                a2[si][rj] += bv[si]*uv[rj];
            }
    }
#pragma unroll
    for (int si = 0; si < 2; si++) {
        int s = sg*2 + si;
        long long rb = (long long)(n*32 + s) * 512;
#pragma unroll
        for (int rj = 0; rj < 2; rj++) {
            int r = rg*2 + rj;
            float c  = d_cos[s*16 + r];
            float sn = d_sin[s*16 + r];
            float xl = a1[si][rj], xh = a1[si][rj+2];
            float yl = a2[si][rj], yh = a2[si][rj+2];
            int col = h*32 + r;
            st_split(d_ga0_c, d_ga1_c, rb + col,        xl*c + xh*sn);
            st_split(d_ga0_c, d_ga1_c, rb + col + 16,   xh*c - xl*sn);
            st_split(d_ga0_c, d_ga1_c, rb + 256 + col,      yl*c - yh*sn);
            st_split(d_ga0_c, d_ga1_c, rb + 256 + col + 16, yh*c + yl*sn);
        }
    }
}

// ---------------- launch ---------------------------------------------------
extern "C" void kernel_launch(void* const* d_in, const int* in_sizes, int n_in,
                              void* d_out, int out_size)
{
    const float* qz = (const float*)d_in[0];
    const float* mask_t = (const float*)d_in[1];
    const float* mask_c = (const float*)d_in[2];
    const float* u_t = (const float*)d_in[3];
    const float* v_t = (const float*)d_in[4];
    const float* u_c = (const float*)d_in[5];
    const float* v_c = (const float*)d_in[6];
    float* out = (float*)d_out;

    cudaFuncSetAttribute(k_proj_mma, cudaFuncAttributeMaxDynamicSharedMemorySize, PROJ_SMEM);
    cudaFuncSetAttribute(k_final_mma, cudaFuncAttributeMaxDynamicSharedMemorySize, FIN_SMEM);
    cudaFuncSetAttribute(k_gt_mma, cudaFuncAttributeMaxDynamicSharedMemorySize, GT_SMEM);

    k_setup<<<8, 256>>>();
    k_split_qz<<<8192, 256>>>(qz);
    k_split_w<<<512, 256>>>(u_t, v_t, 0);
    k_proj_mma<<<dim3(4, 256), 256, PROJ_SMEM>>>(0);   // ncu target
    k_split_w<<<512, 256>>>(u_c, v_c, 1);
    k_proj_mma<<<dim3(4, 256), 256, PROJ_SMEM>>>(1);

    k_split_wf<<<512, 256>>>(u_t, v_t, 0);
    k_ft<<<NT*HH, 256>>>(mask_t);
    k_fc<<<NC*HH, 256>>>(mask_c);

    k_softmax<<<32768, 256>>>();

    k_gt_mma<<<NT*HH, 256, GT_SMEM>>>();
    k_gc<<<NC*HH, 128>>>();

    k_split_wf<<<512, 256>>>(u_c, v_c, 1);
    k_final_mma<<<dim3(2, 256), 256, FIN_SMEM>>>(out, 0);
    k_final_mma<<<dim3(2, 256), 256, FIN_SMEM>>>(out + OUT_HALF, 1);
}

// round 16
// speedup vs baseline: 1.1798x; 1.0023x over previous
#include <cuda_runtime.h>
#include <cuda_bf16.h>

typedef unsigned int u32;
typedef unsigned long long u64;

// Problem constants
#define BB 8
#define CC 32
#define PP 128
#define DD 256
#define HH 8
#define RR 32
#define NT (BB*CC)
#define NC (BB*PP)
#define ROWS 32768
#define OUT_HALF (BB*CC*PP*DD)

// ---------------- scratch ----------------
__device__ __align__(256) float d_qur_t[NT*HH*PP*RR];
__device__ __align__(256) float d_quo_t[NT*HH*PP*RR];
__device__ __align__(256) float d_qvr_t[NT*HH*PP*RR];
__device__ __align__(256) float d_qur_c[NC*HH*CC*RR];
__device__ __align__(256) float d_quo_c[NC*HH*CC*RR];
__device__ __align__(256) float d_qvr_c[NC*HH*CC*RR];
__device__ __align__(256) float d_F_t[NT*HH*PP*PP];
__device__ __align__(256) float d_F_c[NC*HH*CC*CC];
__device__ __align__(256) float d_cos[PP*16];
__device__ __align__(256) float d_sin[PP*16];

__device__ __align__(256) __nv_bfloat16 d_qz0[ROWS*256];
__device__ __align__(256) __nv_bfloat16 d_qz1[ROWS*256];
__device__ __align__(256) __nv_bfloat16 d_qz2[ROWS*256];
__device__ __align__(256) __nv_bfloat16 d_wp_t[3][512*256];
__device__ __align__(256) __nv_bfloat16 d_wp_c[3][512*256];
__device__ __align__(256) __nv_bfloat16 d_wf_t[2][256*512];
__device__ __align__(256) __nv_bfloat16 d_wf_c[2][256*512];
__device__ __align__(256) __nv_bfloat16 d_ga0_t[ROWS*512];
__device__ __align__(256) __nv_bfloat16 d_ga1_t[ROWS*512];
__device__ __align__(256) __nv_bfloat16 d_ga0_c[ROWS*512];
__device__ __align__(256) __nv_bfloat16 d_ga1_c[ROWS*512];

// ---------------- HMMA + cp.async helpers (baseline PTX) -------------------
__device__ __forceinline__ void ldm_x4(u32* r, u32 addr) {
    asm volatile("ldmatrix.sync.aligned.m8n8.x4.shared.b16 {%0, %1, %2, %3}, [%4];" : "=r"(r[0]), "=r"(r[1]), "=r"(r[2]), "=r"(r[3]) : "r"(addr));
}
__device__ __forceinline__ void ldm_x4_t(u32* r, u32 addr) {
    asm volatile("ldmatrix.sync.aligned.m8n8.x4.trans.shared.b16 {%0, %1, %2, %3}, [%4];" : "=r"(r[0]), "=r"(r[1]), "=r"(r[2]), "=r"(r[3]) : "r"(addr));
}
__device__ __forceinline__ void mma_bf16(float* d, const u32* a, const u32* b) {
    asm volatile("mma.sync.aligned.m16n8k16.row.col.f32.bf16.bf16.f32 {%0, %1, %2, %3}, {%4, %5, %6, %7}, {%8, %9}, {%0, %1, %2, %3};" : "+f"(d[0]), "+f"(d[1]), "+f"(d[2]), "+f"(d[3]) : "r"(a[0]), "r"(a[1]), "r"(a[2]), "r"(a[3]), "r"(b[0]), "r"(b[1]));
}
__device__ __forceinline__ void cpa(u32 s, const __nv_bfloat16* g) {
    asm volatile("cp.async.ca.shared.global [%0], [%1], 16;" :: "r"(s), "l"((u64)__cvta_generic_to_global((void*)g)) : "memory");
}
__device__ __forceinline__ void cpa_commit() { asm volatile("cp.async.commit_group;" ::: "memory"); }
__device__ __forceinline__ void cpa_wait0() { asm volatile("cp.async.wait_group 0;" ::: "memory"); }
__device__ __forceinline__ void cpa_wait1() { asm volatile("cp.async.wait_group 1;" ::: "memory"); }

// 64B-stride tiles with chunk swizzle
#define TILE_BYTES 8192
#define SWZ(row, seg) (((seg) ^ (((row) >> 1) & 3)))
#define PROJ_SMEM (2*6*TILE_BYTES)
#define FIN_SMEM  (2*4*TILE_BYTES)
#define FT_SMEM   (6*TILE_BYTES)     // 48 KB: 3 qur splits + 3 qvr splits

// k_gt_mma smem (natural layouts; stride 272B QH / 80B V,U)
#define GQH0 0
#define GQH1 34816
#define GV0  69632
#define GV1  79872
#define GU0  90112
#define GU1  100352
#define GT_SMEM 110592

__device__ __forceinline__ void st_split(__nv_bfloat16* A0, __nv_bfloat16* A1,
                                         long long i, float x) {
    __nv_bfloat16 b0 = __float2bfloat16(x);
    A0[i] = b0;
    A1[i] = __float2bfloat16(x - __bfloat162float(b0));
}

// ---------------- rope table ----------------
__global__ void k_setup() {
    int idx = blockIdx.x * blockDim.x + threadIdx.x;
    if (idx < PP*16) {
        int s = idx >> 4, i = idx & 15;
        double invf = pow(10000.0, -((double)(2*i)) / 32.0);
        double a = (double)s * invf;
        d_cos[idx] = (float)cos(a);
        d_sin[idx] = (float)sin(a);
    }
}

// ---------------- split qz into 3 bf16 components --------------------------
__global__ __launch_bounds__(256) void k_split_qz(const float* __restrict__ qz) {
    int i = (blockIdx.x * 256 + threadIdx.x) * 4;
    float4 x = *reinterpret_cast<const float4*>(qz + i);
    float xs[4];
    xs[0] = x.x; xs[1] = x.y; xs[2] = x.z; xs[3] = x.w;
    __align__(8) __nv_bfloat16 b0[4], b1[4], b2[4];
#pragma unroll
    for (int j = 0; j < 4; j++) {
        b0[j] = __float2bfloat16(xs[j]);
        float r = xs[j] - __bfloat162float(b0[j]);
        b1[j] = __float2bfloat16(r);
        b2[j] = __float2bfloat16(r - __bfloat162float(b1[j]));
    }
    *reinterpret_cast<uint2*>(&d_qz0[i]) = *reinterpret_cast<uint2*>(b0);
    *reinterpret_cast<uint2*>(&d_qz1[i]) = *reinterpret_cast<uint2*>(b1);
    *reinterpret_cast<uint2*>(&d_qz2[i]) = *reinterpret_cast<uint2*>(b2);
}

__global__ __launch_bounds__(256) void k_split_w(const float* __restrict__ U,
                                                 const float* __restrict__ V, int branch) {
    int idx = blockIdx.x * 256 + threadIdx.x;
    int n = idx >> 8, k = idx & 255;
    float x = (n < 256) ? U[n*256 + k] : V[(n-256)*256 + k];
    __nv_bfloat16* w0 = branch ? d_wp_c[0] : d_wp_t[0];
    __nv_bfloat16* w1 = branch ? d_wp_c[1] : d_wp_t[1];
    __nv_bfloat16* w2 = branch ? d_wp_c[2] : d_wp_t[2];
    __nv_bfloat16 b0 = __float2bfloat16(x);
    float r = x - __bfloat162float(b0);
    __nv_bfloat16 b1 = __float2bfloat16(r);
    w0[idx] = b0; w1[idx] = b1;
    w2[idx] = __float2bfloat16(r - __bfloat162float(b1));
}

__global__ __launch_bounds__(256) void k_split_wf(const float* __restrict__ U,
                                                  const float* __restrict__ V, int branch) {
    int idx = blockIdx.x * 256 + threadIdx.x;
    int n = idx >> 9, k = idx & 511;
    float x = (k < 256) ? U[k*256 + n] : V[(k-256)*256 + n];
    __nv_bfloat16* w0 = branch ? d_wf_c[0] : d_wf_t[0];
    __nv_bfloat16* w1 = branch ? d_wf_c[1] : d_wf_t[1];
    __nv_bfloat16 b0 = __float2bfloat16(x);
    w0[idx] = b0;
    w1[idx] = __float2bfloat16(x - __bfloat162float(b0));
}

// ---------------- proj GEMM (HMMA, cp.async, swizzled smem, fused RoPE) ----
__global__ __launch_bounds__(256, 2) void k_proj_mma(int branch) {
    extern __shared__ char smem[];
    const int tid = threadIdx.x;
    const u32 sbase = (u32)__cvta_generic_to_shared(smem);
    const int n0 = blockIdx.x * 128;
    const int m0 = blockIdx.y * 128;
    const int lane = tid & 31, warp = tid >> 5;
    const int wm = warp >> 1, wn = warp & 1;
    const __nv_bfloat16* W0 = branch ? d_wp_c[0] : d_wp_t[0];
    const __nv_bfloat16* W1 = branch ? d_wp_c[1] : d_wp_t[1];
    const __nv_bfloat16* W2 = branch ? d_wp_c[2] : d_wp_t[2];

    float acc[2][8][4];
#pragma unroll
    for (int mt = 0; mt < 2; mt++)
#pragma unroll
        for (int nt = 0; nt < 8; nt++)
#pragma unroll
            for (int e = 0; e < 4; e++) acc[mt][nt][e] = 0.f;

#pragma unroll 1
    for (int kc = -1; kc < 8; kc++) {
        int ld = kc + 1;
        if (ld < 8) {
            u32 stb = sbase + (u32)(ld & 1) * (6*TILE_BYTES);
#pragma unroll
            for (int t = 0; t < 12; t++) {
                int li = tid + t * 256;
                int seg = li & 3, row = (li >> 2) & 127, tile = li >> 9;
                const __nv_bfloat16* src;
                if (tile < 3) {
                    int grow = m0 + row;
                    if (branch) {
                        int b = grow >> 12, rem = grow & 4095;
                        grow = ((b << 5) + (rem & 31)) * 128 + (rem >> 5);
                    }
                    const __nv_bfloat16* A = (tile == 0) ? d_qz0 : (tile == 1) ? d_qz1 : d_qz2;
                    src = A + (long long)grow * 256 + ld * 32 + seg * 8;
                } else {
                    const __nv_bfloat16* W = (tile == 3) ? W0 : (tile == 4) ? W1 : W2;
                    src = W + (long long)(n0 + row) * 256 + ld * 32 + seg * 8;
                }
                cpa(stb + (u32)(tile * TILE_BYTES + row * 64 + SWZ(row, seg) * 16), src);
            }
            cpa_commit();
        }
        if (kc < 0) continue;
        if (kc < 7) cpa_wait1(); else cpa_wait0();
        __syncthreads();
        u32 stb = sbase + (u32)(kc & 1) * (6*TILE_BYTES);
#pragma unroll
        for (int ks = 0; ks < 2; ks++) {
            int seg = ks * 2 + (lane >> 4);
            u32 afr[3][2][4];
#pragma unroll
            for (int sp = 0; sp < 3; sp++)
#pragma unroll
                for (int mt = 0; mt < 2; mt++) {
                    int row = wm * 32 + mt * 16 + (lane & 15);
                    ldm_x4(afr[sp][mt], stb + sp * TILE_BYTES + row * 64 + SWZ(row, seg) * 16);
                }
#pragma unroll
            for (int sb = 0; sb < 3; sb++) {
                u32 bfr[8][2];
#pragma unroll
                for (int g = 0; g < 4; g++) {
                    u32 tr[4];
                    int row = wn * 64 + g * 16 + (lane & 15);
                    ldm_x4(tr, stb + (3 + sb) * TILE_BYTES + row * 64 + SWZ(row, seg) * 16);
                    bfr[2*g][0] = tr[0];   bfr[2*g][1] = tr[2];
                    bfr[2*g+1][0] = tr[1]; bfr[2*g+1][1] = tr[3];
                }
                int na = 3 - sb;
#pragma unroll
                for (int sa = 0; sa < 3; sa++) {
                    if (sa < na) {
#pragma unroll
                        for (int mt = 0; mt < 2; mt++)
#pragma unroll
                            for (int nt = 0; nt < 8; nt++)
                                mma_bf16(acc[mt][nt], afr[sa][mt], bfr[nt]);
                    }
                }
            }
        }
        __syncthreads();
    }

    // fused RoPE epilogue
    float* OUR = branch ? d_qur_c : d_qur_t;
    float* OUO = branch ? d_quo_c : d_quo_t;
    float* OVR = branch ? d_qvr_c : d_qvr_t;
    const int Sbits = branch ? 5 : 7;
    const int Smask = (1 << Sbits) - 1;
    const int isQV = (n0 >= 256);
#pragma unroll
    for (int mt = 0; mt < 2; mt++) {
        int rA = m0 + wm * 32 + mt * 16 + (lane >> 2);
        int rB = rA + 8;
        int nA = rA >> Sbits, sA = rA & Smask;
        int nB = rB >> Sbits, sB = rB & Smask;
#pragma unroll
        for (int nt = 0; nt < 8; nt++) {
            int colh = (n0 & 255) + wn * 64 + nt * 8;
            int rr = (colh & 31) + (lane & 3) * 2;
            int h = (colh >> 5) & 7;
            float sgn = (rr < 16) ? -1.f : 1.f;
            int ci = rr & 15;
            float cA0 = d_cos[sA*16 + ci],     snA0 = d_sin[sA*16 + ci];
            float cA1 = d_cos[sA*16 + ci + 1], snA1 = d_sin[sA*16 + ci + 1];
            float cB0 = d_cos[sB*16 + ci],     snB0 = d_sin[sB*16 + ci];
            float cB1 = d_cos[sB*16 + ci + 1], snB1 = d_sin[sB*16 + ci + 1];
            float q0 = acc[mt][nt][0], q1 = acc[mt][nt][1];
            float q2 = acc[mt][nt][2], q3 = acc[mt][nt][3];
            float p0 = acc[mt][nt ^ 2][0], p1 = acc[mt][nt ^ 2][1];
            float p2 = acc[mt][nt ^ 2][2], p3 = acc[mt][nt ^ 2][3];
            long long baseA = (((long long)(nA * 8 + h) << Sbits) + sA) * 32 + rr;
            long long baseB = (((long long)(nB * 8 + h) << Sbits) + sB) * 32 + rr;
            if (!isQV) {
                float2 w;
                w.x = q0*cA0 + sgn*p0*snA0; w.y = q1*cA1 + sgn*p1*snA1;
                *reinterpret_cast<float2*>(&OUR[baseA]) = w;
                w.x = q0*cA0 - sgn*p0*snA0; w.y = q1*cA1 - sgn*p1*snA1;
                *reinterpret_cast<float2*>(&OUO[baseA]) = w;
                w.x = q2*cB0 + sgn*p2*snB0; w.y = q3*cB1 + sgn*p3*snB1;
                *reinterpret_cast<float2*>(&OUR[baseB]) = w;
                w.x = q2*cB0 - sgn*p2*snB0; w.y = q3*cB1 - sgn*p3*snB1;
                *reinterpret_cast<float2*>(&OUO[baseB]) = w;
            } else {
                float2 w;
                w.x = q0*cA0 + sgn*p0*snA0; w.y = q1*cA1 + sgn*p1*snA1;
                *reinterpret_cast<float2*>(&OVR[baseA]) = w;
                w.x = q2*cB0 + sgn*p2*snB0; w.y = q3*cB1 + sgn*p3*snB1;
                *reinterpret_cast<float2*>(&OVR[baseB]) = w;
            }
        }
    }
}

// ---------------- final GEMM (HMMA, cp.async, swizzled smem) ---------------
__global__ __launch_bounds__(256, 2) void k_final_mma(float* __restrict__ out, int branch) {
    extern __shared__ char smem[];
    const int tid = threadIdx.x;
    const u32 sbase = (u32)__cvta_generic_to_shared(smem);
    const int n0 = blockIdx.x * 128;
    const int m0 = blockIdx.y * 128;
    const int lane = tid & 31, warp = tid >> 5;
    const int wm = warp >> 1, wn = warp & 1;
    const __nv_bfloat16* G0 = branch ? d_ga0_c : d_ga0_t;
    const __nv_bfloat16* G1 = branch ? d_ga1_c : d_ga1_t;
    const __nv_bfloat16* F0 = branch ? d_wf_c[0] : d_wf_t[0];
    const __nv_bfloat16* F1 = branch ? d_wf_c[1] : d_wf_t[1];

    float acc[2][8][4];
#pragma unroll
    for (int mt = 0; mt < 2; mt++)
#pragma unroll
        for (int nt = 0; nt < 8; nt++)
#pragma unroll
            for (int e = 0; e < 4; e++) acc[mt][nt][e] = 0.f;

#pragma unroll 1
    for (int kc = -1; kc < 16; kc++) {
        int ld = kc + 1;
        if (ld < 16) {
            u32 stb = sbase + (u32)(ld & 1) * (4*TILE_BYTES);
#pragma unroll
            for (int t = 0; t < 8; t++) {
                int li = tid + t * 256;
                int seg = li & 3, row = (li >> 2) & 127, tile = li >> 9;
                const __nv_bfloat16* src;
                if (tile == 0)      src = G0 + (long long)(m0 + row) * 512 + ld * 32 + seg * 8;
                else if (tile == 1) src = G1 + (long long)(m0 + row) * 512 + ld * 32 + seg * 8;
                else if (tile == 2) src = F0 + (long long)(n0 + row) * 512 + ld * 32 + seg * 8;
                else                src = F1 + (long long)(n0 + row) * 512 + ld * 32 + seg * 8;
                cpa(stb + (u32)(tile * TILE_BYTES + row * 64 + SWZ(row, seg) * 16), src);
            }
            cpa_commit();
        }
        if (kc < 0) continue;
        if (kc < 15) cpa_wait1(); else cpa_wait0();
        __syncthreads();
        u32 stb = sbase + (u32)(kc & 1) * (4*TILE_BYTES);
#pragma unroll
        for (int ks = 0; ks < 2; ks++) {
            int seg = ks * 2 + (lane >> 4);
            u32 afr[2][2][4];
#pragma unroll
            for (int sp = 0; sp < 2; sp++)
#pragma unroll
                for (int mt = 0; mt < 2; mt++) {
                    int row = wm * 32 + mt * 16 + (lane & 15);
                    ldm_x4(afr[sp][mt], stb + sp * TILE_BYTES + row * 64 + SWZ(row, seg) * 16);
                }
#pragma unroll
            for (int sb = 0; sb < 2; sb++) {
                u32 bfr[8][2];
#pragma unroll
                for (int g = 0; g < 4; g++) {
                    u32 tr[4];
                    int row = wn * 64 + g * 16 + (lane & 15);
                    ldm_x4(tr, stb + (2 + sb) * TILE_BYTES + row * 64 + SWZ(row, seg) * 16);
                    bfr[2*g][0] = tr[0];   bfr[2*g][1] = tr[2];
                    bfr[2*g+1][0] = tr[1]; bfr[2*g+1][1] = tr[3];
                }
                int na = 2 - sb;
#pragma unroll
                for (int sa = 0; sa < 2; sa++) {
                    if (sa < na) {
#pragma unroll
                        for (int mt = 0; mt < 2; mt++)
#pragma unroll
                            for (int nt = 0; nt < 8; nt++)
                                mma_bf16(acc[mt][nt], afr[sa][mt], bfr[nt]);
                    }
                }
            }
        }
        __syncthreads();
    }
#pragma unroll
    for (int mt = 0; mt < 2; mt++)
#pragma unroll
        for (int nt = 0; nt < 8; nt++) {
            int r = m0 + wm * 32 + mt * 16 + (lane >> 2);
            int c = n0 + wn * 64 + nt * 8 + (lane & 3) * 2;
            long long r0o, r1o;
            if (!branch) {
                r0o = (long long)r; r1o = (long long)(r + 8);
            } else {
                int nn = r >> 5, cc2 = r & 31;
                int b = nn >> 7, p = nn & 127;
                r0o = (long long)((b * 32 + cc2) * 128 + p);
                int r8 = r + 8;
                nn = r8 >> 5; cc2 = r8 & 31; b = nn >> 7; p = nn & 127;
                r1o = (long long)((b * 32 + cc2) * 128 + p);
            }
            float2 lo; lo.x = acc[mt][nt][0]; lo.y = acc[mt][nt][1];
            float2 hi; hi.x = acc[mt][nt][2]; hi.y = acc[mt][nt][3];
            *reinterpret_cast<float2*>(&out[r0o * 256 + c]) = lo;
            *reinterpret_cast<float2*>(&out[r1o * 256 + c]) = hi;
        }
}

// ---------------- F_t (HMMA, in-kernel 3-way split, K=32) ------------------
// F[s][t] = sum_r qur[s][r]*qvr[t][r] + mask;  A=qur natural, B=qvr natural.
__global__ __launch_bounds__(256, 2) void k_ft_mma(const float* __restrict__ mask) {
    extern __shared__ char smem[];
    const int tid = threadIdx.x;
    const u32 sbase = (u32)__cvta_generic_to_shared(smem);
    int nh = blockIdx.x;
    int n = nh >> 3;
    const float* ubase = d_qur_t + nh*4096;
    const float* vbase = d_qvr_t + nh*4096;
    const int lane = tid & 31, warp = tid >> 5;
    const int wm = warp >> 1, wn = warp & 1;

    // load + split: 1024 chunk-tasks (2 ops x 128 rows x 4 segs)
#pragma unroll
    for (int t = 0; t < 4; t++) {
        int li = tid + t * 256;
        int op = li >> 9;
        int task = li & 511;
        int row = task >> 2, seg = task & 3;
        const float* src = (op ? vbase : ubase) + row*32 + seg*8;
        float4 xa = *reinterpret_cast<const float4*>(src);
        float4 xb = *reinterpret_cast<const float4*>(src + 4);
        float xs[8];
        xs[0] = xa.x; xs[1] = xa.y; xs[2] = xa.z; xs[3] = xa.w;
        xs[4] = xb.x; xs[5] = xb.y; xs[6] = xb.z; xs[7] = xb.w;
        __align__(16) __nv_bfloat16 b0[8], b1[8], b2[8];
#pragma unroll
        for (int j = 0; j < 8; j++) {
            b0[j] = __float2bfloat16(xs[j]);
            float r = xs[j] - __bfloat162float(b0[j]);
            b1[j] = __float2bfloat16(r);
            b2[j] = __float2bfloat16(r - __bfloat162float(b1[j]));
        }
        int off = op * (3*TILE_BYTES) + row*64 + SWZ(row, seg)*16;
        *reinterpret_cast<uint4*>(smem + off)                = *reinterpret_cast<uint4*>(b0);
        *reinterpret_cast<uint4*>(smem + off + TILE_BYTES)   = *reinterpret_cast<uint4*>(b1);
        *reinterpret_cast<uint4*>(smem + off + 2*TILE_BYTES) = *reinterpret_cast<uint4*>(b2);
    }
    __syncthreads();

    float acc[2][8][4];
#pragma unroll
    for (int mt = 0; mt < 2; mt++)
#pragma unroll
        for (int nt = 0; nt < 8; nt++)
#pragma unroll
            for (int e = 0; e < 4; e++) acc[mt][nt][e] = 0.f;

#pragma unroll
    for (int ks = 0; ks < 2; ks++) {
        int seg = ks * 2 + (lane >> 4);
        u32 afr[3][2][4];
#pragma unroll
        for (int sp = 0; sp < 3; sp++)
#pragma unroll
            for (int mt = 0; mt < 2; mt++) {
                int row = wm * 32 + mt * 16 + (lane & 15);
                ldm_x4(afr[sp][mt], sbase + sp * TILE_BYTES + row * 64 + SWZ(row, seg) * 16);
            }
#pragma unroll
        for (int sb = 0; sb < 3; sb++) {
            u32 bfr[8][2];
#pragma unroll
            for (int g = 0; g < 4; g++) {
                u32 tr[4];
                int row = wn * 64 + g * 16 + (lane & 15);
                ldm_x4(tr, sbase + (3 + sb) * TILE_BYTES + row * 64 + SWZ(row, seg) * 16);
                bfr[2*g][0] = tr[0];   bfr[2*g][1] = tr[2];
                bfr[2*g+1][0] = tr[1]; bfr[2*g+1][1] = tr[3];
            }
            int na = 3 - sb;
#pragma unroll
            for (int sa = 0; sa < 3; sa++) {
                if (sa < na) {
#pragma unroll
                    for (int mt = 0; mt < 2; mt++)
#pragma unroll
                        for (int nt = 0; nt < 8; nt++)
                            mma_bf16(acc[mt][nt], afr[sa][mt], bfr[nt]);
                }
            }
        }
    }

    // epilogue: F = acc + mask
    float* fout = d_F_t + (long long)nh*16384;
    const float* mrow = mask + (long long)n*16384;
#pragma unroll
    for (int mt = 0; mt < 2; mt++) {
        int s0 = wm * 32 + mt * 16 + (lane >> 2);
#pragma unroll
        for (int nt = 0; nt < 8; nt++) {
            int c = wn * 64 + nt * 8 + (lane & 3) * 2;
            float2 m0v = *reinterpret_cast<const float2*>(mrow + s0*128 + c);
            float2 m1v = *reinterpret_cast<const float2*>(mrow + (s0+8)*128 + c);
            float2 lo; lo.x = acc[mt][nt][0] + m0v.x; lo.y = acc[mt][nt][1] + m0v.y;
            float2 hi; hi.x = acc[mt][nt][2] + m1v.x; hi.y = acc[mt][nt][3] + m1v.y;
            *reinterpret_cast<float2*>(fout + s0*128 + c) = lo;
            *reinterpret_cast<float2*>(fout + (s0+8)*128 + c) = hi;
        }
    }
}

// ---------------- F_c -------------------------------------------------------
__global__ __launch_bounds__(256) void k_fc(const float* __restrict__ mask) {
    __shared__ float SuT[32][36];
    __shared__ float SvT[32][36];
    int nh = blockIdx.x;
    int n = nh >> 3;
    const float* ubase = d_qur_c + nh*1024;
    const float* vbase = d_qvr_c + nh*1024;
    int tid = threadIdx.x;
    {
        int s = tid >> 3, rq = (tid & 7) << 2;
        float4 u = *reinterpret_cast<const float4*>(ubase + s*32 + rq);
        SuT[rq][s] = u.x; SuT[rq+1][s] = u.y; SuT[rq+2][s] = u.z; SuT[rq+3][s] = u.w;
        float4 v = *reinterpret_cast<const float4*>(vbase + s*32 + rq);
        SvT[rq][s] = v.x; SvT[rq+1][s] = v.y; SvT[rq+2][s] = v.z; SvT[rq+3][s] = v.w;
    }
    __syncthreads();
    int tx = tid & 7, ty = tid >> 3;
    float acc[4];
    acc[0] = 0.f; acc[1] = 0.f; acc[2] = 0.f; acc[3] = 0.f;
#pragma unroll
    for (int k = 0; k < 32; k++) {
        float a = SuT[k][ty];
        float4 b = *(const float4*)&SvT[k][tx*4];
        acc[0] += a*b.x; acc[1] += a*b.y; acc[2] += a*b.z; acc[3] += a*b.w;
    }
    int t0 = tx*4;
    float4 m4 = *reinterpret_cast<const float4*>(mask + (long long)n*1024 + ty*32 + t0);
    float4 o;
    o.x = acc[0] + m4.x; o.y = acc[1] + m4.y; o.z = acc[2] + m4.z; o.w = acc[3] + m4.w;
    *reinterpret_cast<float4*>(d_F_c + (long long)nh*1024 + ty*32 + t0) = o;
}

// ---------------- joint softmax --------------------------------------------
__global__ __launch_bounds__(256) void k_softmax() {
    int warp = threadIdx.x >> 5, lane = threadIdx.x & 31;
    int rowid = blockIdx.x * 8 + warp;
    int p  = rowid & 127;
    int r1 = rowid >> 7;
    int c  = r1 & 31;
    int r2 = r1 >> 5;
    int h  = r2 & 7;
    int b  = r2 >> 3;
    float* ft = d_F_t + ((long long)(((b*32 + c)*8 + h)*128 + p))*128;
    float* fc = d_F_c + ((long long)(((b*128 + p)*8 + h)*32 + c))*32;
    float v[5];
    v[0] = ft[lane]; v[1] = ft[lane+32]; v[2] = ft[lane+64]; v[3] = ft[lane+96];
    v[4] = fc[lane];
    float m = v[0];
#pragma unroll
    for (int i = 1; i < 5; i++) m = fmaxf(m, v[i]);
#pragma unroll
    for (int off = 16; off >= 1; off >>= 1)
        m = fmaxf(m, __shfl_xor_sync(0xffffffffu, m, off));
    float sum = 0.f;
#pragma unroll
    for (int i = 0; i < 5; i++) { v[i] = expf(256.f*(v[i] - m)); sum += v[i]; }
#pragma unroll
    for (int off = 16; off >= 1; off >>= 1)
        sum += __shfl_xor_sync(0xffffffffu, sum, off);
    float inv = 1.f / sum;
    ft[lane]     = v[0]*inv;
    ft[lane+32]  = v[1]*inv;
    ft[lane+64]  = v[2]*inv;
    ft[lane+96]  = v[3]*inv;
    fc[lane]     = v[4]*inv;
}

// ---------------- G time (HMMA, natural tiles + ldmatrix.trans) ------------
__global__ __launch_bounds__(256, 2) void k_gt_mma() {
    extern __shared__ char smem[];
    const int tid = threadIdx.x;
    const u32 sbase = (u32)__cvta_generic_to_shared(smem);
    int nh = blockIdx.x;
    int n = nh >> 3, h = nh & 7;
    const float* qh = d_F_t + (long long)nh*16384;
    const float* vb = d_qvr_t + nh*4096;
    const float* ub = d_quo_t + nh*4096;
    const int lane = tid & 31, warp = tid >> 5;

#pragma unroll
    for (int t = 0; t < 16; t++) {
        int li = tid + t * 256;
        int row = li >> 5, c4 = li & 31;
        float4 x = *reinterpret_cast<const float4*>(qh + row*128 + c4*4);
        float xs[4];
        xs[0] = x.x; xs[1] = x.y; xs[2] = x.z; xs[3] = x.w;
        __align__(8) __nv_bfloat16 b0[4], b1[4];
#pragma unroll
        for (int j = 0; j < 4; j++) {
            b0[j] = __float2bfloat16(xs[j]);
            b1[j] = __float2bfloat16(xs[j] - __bfloat162float(b0[j]));
        }
        int off = row*272 + c4*8;
        *reinterpret_cast<uint2*>(smem + GQH0 + off) = *reinterpret_cast<uint2*>(b0);
        *reinterpret_cast<uint2*>(smem + GQH1 + off) = *reinterpret_cast<uint2*>(b1);
    }
    {
        int row = tid >> 1, half = tid & 1;
#pragma unroll
        for (int j = 0; j < 4; j++) {
            float4 x = *reinterpret_cast<const float4*>(vb + row*32 + half*16 + j*4);
            float xs[4];
            xs[0] = x.x; xs[1] = x.y; xs[2] = x.z; xs[3] = x.w;
            __align__(8) __nv_bfloat16 b0[4], b1[4];
#pragma unroll
            for (int e = 0; e < 4; e++) {
                b0[e] = __float2bfloat16(xs[e]);
                b1[e] = __float2bfloat16(xs[e] - __bfloat162float(b0[e]));
            }
            int off = row*80 + (half*16 + j*4)*2;
            *reinterpret_cast<uint2*>(smem + GV0 + off) = *reinterpret_cast<uint2*>(b0);
            *reinterpret_cast<uint2*>(smem + GV1 + off) = *reinterpret_cast<uint2*>(b1);
        }
#pragma unroll
        for (int j = 0; j < 4; j++) {
            float4 x = *reinterpret_cast<const float4*>(ub + row*32 + half*16 + j*4);
            float xs[4];
            xs[0] = x.x; xs[1] = x.y; xs[2] = x.z; xs[3] = x.w;
            __align__(8) __nv_bfloat16 b0[4], b1[4];
#pragma unroll
            for (int e = 0; e < 4; e++) {
                b0[e] = __float2bfloat16(xs[e]);
                b1[e] = __float2bfloat16(xs[e] - __bfloat162float(b0[e]));
            }
            int off = row*80 + (half*16 + j*4)*2;
            *reinterpret_cast<uint2*>(smem + GU0 + off) = *reinterpret_cast<uint2*>(b0);
            *reinterpret_cast<uint2*>(smem + GU1 + off) = *reinterpret_cast<uint2*>(b1);
        }
    }
    __syncthreads();

    float acc[2][4][4];
#pragma unroll
    for (int mt = 0; mt < 2; mt++)
#pragma unroll
        for (int nt = 0; nt < 4; nt++)
#pragma unroll
            for (int e = 0; e < 4; e++) acc[mt][nt][e] = 0.f;

    int trow = (lane & 7) + ((lane >> 4) << 3);
    int tcol8 = ((lane >> 3) & 1) * 8;

    if (warp < 4) {
        u32 wbase = (u32)warp * 32;
#pragma unroll
        for (int k0 = 0; k0 < 8; k0++) {
            u32 a[2][2][4];
#pragma unroll
            for (int sp = 0; sp < 2; sp++)
#pragma unroll
                for (int mt = 0; mt < 2; mt++)
                    ldm_x4(a[sp][mt], sbase + (sp ? GQH1 : GQH0)
                           + (wbase + mt*16 + (lane & 15))*272 + k0*32 + (lane >> 4)*16);
            u32 b[2][4][2];
#pragma unroll
            for (int sp = 0; sp < 2; sp++)
#pragma unroll
                for (int rb = 0; rb < 2; rb++) {
                    u32 tr[4];
                    ldm_x4_t(tr, sbase + (sp ? GV1 : GV0)
                             + (k0*16 + trow)*80 + (rb*16 + tcol8)*2);
                    b[sp][2*rb][0] = tr[0];   b[sp][2*rb][1] = tr[2];
                    b[sp][2*rb+1][0] = tr[1]; b[sp][2*rb+1][1] = tr[3];
                }
#pragma unroll
            for (int mt = 0; mt < 2; mt++)
#pragma unroll
                for (int nt = 0; nt < 4; nt++) {
                    mma_bf16(acc[mt][nt], a[0][mt], b[0][nt]);
                    mma_bf16(acc[mt][nt], a[0][mt], b[1][nt]);
                    mma_bf16(acc[mt][nt], a[1][mt], b[0][nt]);
                }
        }
#pragma unroll
        for (int mt = 0; mt < 2; mt++) {
            int s0 = (int)wbase + mt*16 + (lane >> 2);
#pragma unroll
            for (int nt = 0; nt < 2; nt++) {
                int rbase = nt*8 + (lane & 3)*2;
#pragma unroll
                for (int e = 0; e < 4; e++) {
                    int s = s0 + ((e >> 1) << 3);
                    int ci = rbase + (e & 1);
                    float c = d_cos[s*16 + ci], sn = d_sin[s*16 + ci];
                    float xl = acc[mt][nt][e], xh = acc[mt][nt+2][e];
                    long long rb2 = (long long)(n*128 + s) * 512;
                    int col = h*32 + ci;
                    st_split(d_ga0_t, d_ga1_t, rb2 + col,      xl*c + xh*sn);
                    st_split(d_ga0_t, d_ga1_t, rb2 + col + 16, xh*c - xl*sn);
                }
            }
        }
    } else {
        u32 sb_s = (u32)(warp - 4) * 32;
#pragma unroll
        for (int k0 = 0; k0 < 8; k0++) {
            u32 a[2][2][4];
#pragma unroll
            for (int sp = 0; sp < 2; sp++)
#pragma unroll
                for (int mt = 0; mt < 2; mt++)
                    ldm_x4_t(a[sp][mt], sbase + (sp ? GU1 : GU0)
                             + (k0*16 + trow)*80 + (mt*16 + tcol8)*2);
            u32 b[2][4][2];
#pragma unroll
            for (int sp = 0; sp < 2; sp++)
#pragma unroll
                for (int sb8 = 0; sb8 < 2; sb8++) {
                    u32 tr[4];
                    ldm_x4_t(tr, sbase + (sp ? GQH1 : GQH0)
                             + (k0*16 + trow)*272 + (sb_s + sb8*16 + tcol8)*2);
                    b[sp][2*sb8][0] = tr[0];   b[sp][2*sb8][1] = tr[2];
                    b[sp][2*sb8+1][0] = tr[1]; b[sp][2*sb8+1][1] = tr[3];
                }
#pragma unroll
            for (int mt = 0; mt < 2; mt++)
#pragma unroll
                for (int nt = 0; nt < 4; nt++) {
                    mma_bf16(acc[mt][nt], a[0][mt], b[0][nt]);
                    mma_bf16(acc[mt][nt], a[0][mt], b[1][nt]);
                    mma_bf16(acc[mt][nt], a[1][mt], b[0][nt]);
                }
        }
#pragma unroll
        for (int nt = 0; nt < 4; nt++) {
            int sb = (int)sb_s + nt*8 + (lane & 3)*2;
#pragma unroll
            for (int e = 0; e < 4; e++) {
                int s = sb + (e & 1);
                int r = (lane >> 2) + ((e >> 1) << 3);
                float c = d_cos[s*16 + r], sn = d_sin[s*16 + r];
                float yl = acc[0][nt][e], yh = acc[1][nt][e];
                long long rb2 = (long long)(n*128 + s) * 512;
                int col = 256 + h*32 + r;
                st_split(d_ga0_t, d_ga1_t, rb2 + col,      yl*c - yh*sn);
                st_split(d_ga0_t, d_ga1_t, rb2 + col + 16, yh*c + yl*sn);
            }
        }
    }
}

// ---------------- G chan (FFMA, small) --------------------------------------
__global__ __launch_bounds__(128) void k_gc() {
    __shared__ float Qn[32][34];
    __shared__ float Vs[32][34];
    __shared__ float Us[32][34];
    int nh = blockIdx.x;
    int n = nh >> 3, h = nh & 7;
    const float* qh = d_F_c + (long long)nh*1024;
    const float* vb = d_qvr_c + nh*1024;
    const float* ub = d_quo_c + nh*1024;
    int tid = threadIdx.x;
#pragma unroll
    for (int l = 0; l < 2; l++) {
        int lin = tid + l*128;
        int t = lin >> 3, sq = (lin & 7) << 2;
        float4 q = *(const float4*)(qh + t*32 + sq);
        Qn[t][sq] = q.x; Qn[t][sq+1] = q.y; Qn[t][sq+2] = q.z; Qn[t][sq+3] = q.w;
        float4 v = *(const float4*)(vb + t*32 + sq);
        Vs[t][sq] = v.x; Vs[t][sq+1] = v.y; Vs[t][sq+2] = v.z; Vs[t][sq+3] = v.w;
        float4 u = *(const float4*)(ub + t*32 + sq);
        Us[t][sq] = u.x; Us[t][sq+1] = u.y; Us[t][sq+2] = u.z; Us[t][sq+3] = u.w;
    }
    __syncthreads();
    int rg = tid & 7, sg = tid >> 3;
    float a1[2][4], a2[2][4];
#pragma unroll
    for (int i = 0; i < 2; i++)
#pragma unroll
        for (int j = 0; j < 4; j++) { a1[i][j] = 0.f; a2[i][j] = 0.f; }
#pragma unroll
    for (int t = 0; t < 32; t++) {
        float av[2], bv[2], vv[4], uv[4];
        av[0] = Qn[sg*2][t];
        av[1] = Qn[sg*2+1][t];
        float2 qb = *(const float2*)&Qn[t][sg*2];
        float2 v0 = *(const float2*)&Vs[t][rg*2];
        float2 v1 = *(const float2*)&Vs[t][rg*2+16];
        float2 u0 = *(const float2*)&Us[t][rg*2];
        float2 u1 = *(const float2*)&Us[t][rg*2+16];
        bv[0] = qb.x; bv[1] = qb.y;
        vv[0] = v0.x; vv[1] = v0.y; vv[2] = v1.x; vv[3] = v1.y;
        uv[0] = u0.x; uv[1] = u0.y; uv[2] = u1.x; uv[3] = u1.y;
#pragma unroll
        for (int si = 0; si < 2; si++)
#pragma unroll
            for (int rj = 0; rj < 4; rj++) {
                a1[si][rj] += av[si]*vv[rj];
                a2[si][rj] += bv[si]*uv[rj];
            }
    }
#pragma unroll
    for (int si = 0; si < 2; si++) {
        int s = sg*2 + si;
        long long rb = (long long)(n*32 + s) * 512;
#pragma unroll
        for (int rj = 0; rj < 2; rj++) {
            int r = rg*2 + rj;
            float c  = d_cos[s*16 + r];
            float sn = d_sin[s*16 + r];
            float xl = a1[si][rj], xh = a1[si][rj+2];
            float yl = a2[si][rj], yh = a2[si][rj+2];
            int col = h*32 + r;
            st_split(d_ga0_c, d_ga1_c, rb + col,        xl*c + xh*sn);
            st_split(d_ga0_c, d_ga1_c, rb + col + 16,   xh*c - xl*sn);
            st_split(d_ga0_c, d_ga1_c, rb + 256 + col,      yl*c - yh*sn);
            st_split(d_ga0_c, d_ga1_c, rb + 256 + col + 16, yh*c + yl*sn);
        }
    }
}

// ---------------- launch ---------------------------------------------------
extern "C" void kernel_launch(void* const* d_in, const int* in_sizes, int n_in,
                              void* d_out, int out_size)
{
    const float* qz = (const float*)d_in[0];
    const float* mask_t = (const float*)d_in[1];
    const float* mask_c = (const float*)d_in[2];
    const float* u_t = (const float*)d_in[3];
    const float* v_t = (const float*)d_in[4];
    const float* u_c = (const float*)d_in[5];
    const float* v_c = (const float*)d_in[6];
    float* out = (float*)d_out;

    cudaFuncSetAttribute(k_proj_mma, cudaFuncAttributeMaxDynamicSharedMemorySize, PROJ_SMEM);
    cudaFuncSetAttribute(k_final_mma, cudaFuncAttributeMaxDynamicSharedMemorySize, FIN_SMEM);
    cudaFuncSetAttribute(k_ft_mma, cudaFuncAttributeMaxDynamicSharedMemorySize, FT_SMEM);
    cudaFuncSetAttribute(k_gt_mma, cudaFuncAttributeMaxDynamicSharedMemorySize, GT_SMEM);

    k_setup<<<8, 256>>>();
    k_split_qz<<<8192, 256>>>(qz);
    k_split_w<<<512, 256>>>(u_t, v_t, 0);
    k_proj_mma<<<dim3(4, 256), 256, PROJ_SMEM>>>(0);   // ncu target
    k_split_w<<<512, 256>>>(u_c, v_c, 1);
    k_proj_mma<<<dim3(4, 256), 256, PROJ_SMEM>>>(1);

    k_split_wf<<<512, 256>>>(u_t, v_t, 0);
    k_ft_mma<<<NT*HH, 256, FT_SMEM>>>(mask_t);
    k_fc<<<NC*HH, 256>>>(mask_c);

    k_softmax<<<32768, 256>>>();

    k_gt_mma<<<NT*HH, 256, GT_SMEM>>>();
    k_gc<<<NC*HH, 128>>>();

    k_split_wf<<<512, 256>>>(u_c, v_c, 1);
    k_final_mma<<<dim3(2, 256), 256, FIN_SMEM>>>(out, 0);
    k_final_mma<<<dim3(2, 256), 256, FIN_SMEM>>>(out + OUT_HALF, 1);
}